// round 5
// baseline (speedup 1.0000x reference)
#include <cuda_runtime.h>
#include <cstdint>
#include <cstddef>

// ---------------------------------------------------------------------------
// FFTAttention: fft2 -> GroupNorm -> QKV gemm -> attention -> proj -> ifft2
// b=8, c=256, h=w=32, n=2048, heads=4, ch=64.
// Matmuls via tf32 mma; hi/lo splits interleaved as float2 (LDS.64 fragments).
// ---------------------------------------------------------------------------

#define NTOK 2048

__device__ float g_xr  [8 * 256 * NTOK];
__device__ float g_qkv [8 * 768 * NTOK];
__device__ float g_attn[8 * 256 * NTOK];
__device__ float g_proj[8 * 256 * NTOK];
__device__ float g_alpha[8 * 256];
__device__ float g_beta [8 * 256];
__device__ float g_bb   [8 * 768];
__device__ float g_stats[512];

// ---------------- tf32 helpers ----------------
__device__ __forceinline__ uint32_t f2tf(float x) {
    uint32_t r;
    asm("cvt.rna.tf32.f32 %0, %1;" : "=r"(r) : "f"(x));
    return r;
}
__device__ __forceinline__ void split_tf(float x, uint32_t& hi, uint32_t& lo) {
    hi = f2tf(x);
    lo = f2tf(x - __uint_as_float(hi));
}
__device__ __forceinline__ void split4(float4 v, float4& h, float4& l) {
    uint32_t a, b;
    split_tf(v.x, a, b); h.x = __uint_as_float(a); l.x = __uint_as_float(b);
    split_tf(v.y, a, b); h.y = __uint_as_float(a); l.y = __uint_as_float(b);
    split_tf(v.z, a, b); h.z = __uint_as_float(a); l.z = __uint_as_float(b);
    split_tf(v.w, a, b); h.w = __uint_as_float(a); l.w = __uint_as_float(b);
}
// write split as interleaved (hi,lo) float2 pairs: two float4 stores
__device__ __forceinline__ void store_ilv(float* dst, float4 h, float4 l) {
    *(float4*)(dst)     = make_float4(h.x, l.x, h.y, l.y);
    *(float4*)(dst + 4) = make_float4(h.z, l.z, h.w, l.w);
}
__device__ __forceinline__ void mma8(float* d, const uint32_t* a, const uint32_t* b) {
    asm volatile(
        "mma.sync.aligned.m16n8k8.row.col.f32.tf32.tf32.f32 "
        "{%0,%1,%2,%3}, {%4,%5,%6,%7}, {%8,%9}, {%0,%1,%2,%3};\n"
        : "+f"(d[0]), "+f"(d[1]), "+f"(d[2]), "+f"(d[3])
        : "r"(a[0]), "r"(a[1]), "r"(a[2]), "r"(a[3]), "r"(b[0]), "r"(b[1]));
}

__global__ void k_zero_stats() { g_stats[threadIdx.x] = 0.f; }

// ---------------------------------------------------------------------------
// Forward FFT2 + groupnorm stats (one warp per (b,c) image)
// ---------------------------------------------------------------------------
__global__ void __launch_bounds__(32) k_fft(const float* __restrict__ x) {
    __shared__ float sr[32][33];
    __shared__ float si[32][33];
    __shared__ float2 tw[32];

    int img  = blockIdx.x;
    int lane = threadIdx.x;

    float sn, cs;
    __sincosf(-6.283185307179586f * (float)lane / 32.f, &sn, &cs);
    tw[lane] = make_float2(cs, sn);

    const float* xin = x + (size_t)img * 1024;
#pragma unroll
    for (int y = 0; y < 32; y++) sr[y][lane] = xin[y * 32 + lane];
    __syncwarp();

    float vr[32];
#pragma unroll
    for (int j = 0; j < 32; j++) vr[j] = sr[lane][j];
    __syncwarp();

    for (int k = 0; k < 32; k++) {
        float ar = 0.f, ai = 0.f;
#pragma unroll
        for (int j = 0; j < 32; j++) {
            float2 w = tw[(j * k) & 31];
            ar += vr[j] * w.x;
            ai += vr[j] * w.y;
        }
        sr[k][lane] = ar;
        si[k][lane] = ai;
    }
    __syncwarp();

    float cr[32], ci[32];
#pragma unroll
    for (int t = 0; t < 32; t++) { cr[t] = sr[lane][t]; ci[t] = si[lane][t]; }

    float* outp = g_xr + (size_t)img * NTOK;
    float sum = 0.f, ssq = 0.f;
    for (int k = 0; k < 32; k++) {
        float ar = 0.f, ai = 0.f;
#pragma unroll
        for (int j = 0; j < 32; j++) {
            float2 w = tw[(j * k) & 31];
            ar += cr[j] * w.x - ci[j] * w.y;
            ai += cr[j] * w.y + ci[j] * w.x;
        }
        outp[(k * 32 + lane) * 2 + 0] = ar;
        outp[(k * 32 + lane) * 2 + 1] = ai;
        sum += ar + ai;
        ssq += ar * ar + ai * ai;
    }

#pragma unroll
    for (int off = 16; off > 0; off >>= 1) {
        sum += __shfl_xor_sync(0xffffffffu, sum, off);
        ssq += __shfl_xor_sync(0xffffffffu, ssq, off);
    }
    if (lane == 0) {
        int b  = img >> 8;
        int ch = img & 255;
        int grp = b * 32 + (ch >> 3);
        atomicAdd(&g_stats[grp * 2 + 0], sum);
        atomicAdd(&g_stats[grp * 2 + 1], ssq);
    }
}

__global__ void k_prep_ab(const float* __restrict__ gn_w, const float* __restrict__ gn_b) {
    int b = blockIdx.x;
    int c = threadIdx.x;
    int grp = b * 32 + (c >> 3);
    float s0 = g_stats[grp * 2 + 0];
    float s1 = g_stats[grp * 2 + 1];
    float mean = s0 * (1.f / 16384.f);
    float var  = s1 * (1.f / 16384.f) - mean * mean;
    float rs   = rsqrtf(var + 1e-5f);
    float w = gn_w[c];
    g_alpha[b * 256 + c] = rs * w;
    g_beta [b * 256 + c] = gn_b[c] - mean * rs * w;
}

__global__ void __launch_bounds__(256) k_prep_bb(const float* __restrict__ qkv_w,
                                                 const float* __restrict__ qkv_b) {
    int w = (blockIdx.x * 256 + threadIdx.x) >> 5;
    int lane = threadIdx.x & 31;
    int b = w / 768, o = w - b * 768;
    const float* wr = qkv_w + (size_t)o * 256;
    const float* be = g_beta + b * 256;
    float acc = 0.f;
#pragma unroll
    for (int c = lane; c < 256; c += 32) acc += wr[c] * be[c];
#pragma unroll
    for (int off = 16; off > 0; off >>= 1) acc += __shfl_xor_sync(0xffffffffu, acc, off);
    if (lane == 0) g_bb[w] = acc + qkv_b[o];
}

// ---------------------------------------------------------------------------
// tf32 3x GEMM, interleaved hi/lo tiles. block 128x128, 8 warps, warp 64x32.
// ---------------------------------------------------------------------------
#define GA2 34     // A row stride, float2 units (32 k + pad)
#define GB2 132    // B row stride, float2 units (128 n + pad)
#define GEMM_SMEM ((128 * GA2 + 32 * GB2) * 8)

__global__ void __launch_bounds__(256, 2) k_gemm_t(
    const float* __restrict__ A, const float* __restrict__ X,
    const float* __restrict__ alpha, const float* __restrict__ bias,
    int M, int biasPerBatch, float* __restrict__ out)
{
    extern __shared__ float2 sg2[];
    float2* A2 = sg2;                 // [128][GA2] (m, k) hi/lo pairs
    float2* B2 = sg2 + 128 * GA2;     // [32][GB2]  (k, n) hi/lo pairs

    int n0 = blockIdx.x * 128, o0 = blockIdx.y * 128, bb = blockIdx.z;
    int tid = threadIdx.x, lane = tid & 31, wid = tid >> 5;
    int wm = wid >> 2, wn = wid & 3;
    int lq = lane >> 2, lr = lane & 3;
    const float* Xb = X + (size_t)bb * 256 * NTOK;
    bool useAlpha = (alpha != nullptr);

    float acc[4][4][4];
#pragma unroll
    for (int i = 0; i < 4; i++)
#pragma unroll
        for (int j = 0; j < 4; j++)
#pragma unroll
            for (int r = 0; r < 4; r++) acc[i][j][r] = 0.f;

    for (int k0 = 0; k0 < 256; k0 += 32) {
        __syncthreads();
#pragma unroll
        for (int r = 0; r < 4; r++) {
            int idx = tid + r * 256;
            int row = idx >> 3, k4 = (idx & 7) << 2;
            float4 v = *(const float4*)(A + (size_t)(o0 + row) * 256 + k0 + k4);
            float4 h, l; split4(v, h, l);
            store_ilv((float*)(A2 + row * GA2 + k4), h, l);
        }
#pragma unroll
        for (int r = 0; r < 4; r++) {
            int idx = tid + r * 256;
            int kr = idx >> 5, n4 = (idx & 31) << 2;
            float4 v = *(const float4*)(Xb + (size_t)(k0 + kr) * NTOK + n0 + n4);
            float al = useAlpha ? alpha[bb * 256 + k0 + kr] : 1.f;
            v.x *= al; v.y *= al; v.z *= al; v.w *= al;
            float4 h, l; split4(v, h, l);
            store_ilv((float*)(B2 + kr * GB2 + n4), h, l);
        }
        __syncthreads();

#pragma unroll
        for (int kk = 0; kk < 4; kk++) {
            uint32_t ah[4][4], al_[4][4];
#pragma unroll
            for (int mf = 0; mf < 4; mf++) {
                int m = wm * 64 + mf * 16 + lq;
                int base = m * GA2 + kk * 8 + lr;
                float2 x0 = A2[base];
                float2 x1 = A2[base + 8 * GA2];
                float2 x2 = A2[base + 4];
                float2 x3 = A2[base + 8 * GA2 + 4];
                ah[mf][0] = __float_as_uint(x0.x); al_[mf][0] = __float_as_uint(x0.y);
                ah[mf][1] = __float_as_uint(x1.x); al_[mf][1] = __float_as_uint(x1.y);
                ah[mf][2] = __float_as_uint(x2.x); al_[mf][2] = __float_as_uint(x2.y);
                ah[mf][3] = __float_as_uint(x3.x); al_[mf][3] = __float_as_uint(x3.y);
            }
#pragma unroll
            for (int nf = 0; nf < 4; nf++) {
                int n = wn * 32 + nf * 8 + lq;
                int bbase = (kk * 8 + lr) * GB2 + n;
                float2 y0 = B2[bbase];
                float2 y1 = B2[bbase + 4 * GB2];
                uint32_t bh[2] = {__float_as_uint(y0.x), __float_as_uint(y1.x)};
                uint32_t bl[2] = {__float_as_uint(y0.y), __float_as_uint(y1.y)};
#pragma unroll
                for (int mf = 0; mf < 4; mf++) {
                    mma8(acc[mf][nf], ah[mf], bh);
                    mma8(acc[mf][nf], al_[mf], bh);
                    mma8(acc[mf][nf], ah[mf], bl);
                }
            }
        }
    }

#pragma unroll
    for (int mf = 0; mf < 4; mf++) {
        int o = o0 + wm * 64 + mf * 16 + lq;
        float b0 = biasPerBatch ? bias[bb * M + o] : bias[o];
        float b1 = biasPerBatch ? bias[bb * M + o + 8] : bias[o + 8];
#pragma unroll
        for (int nf = 0; nf < 4; nf++) {
            int n = n0 + wn * 32 + nf * 8 + 2 * lr;
            float2 v0 = make_float2(acc[mf][nf][0] + b0, acc[mf][nf][1] + b0);
            float2 v1 = make_float2(acc[mf][nf][2] + b1, acc[mf][nf][3] + b1);
            *(float2*)(out + ((size_t)bb * M + o) * NTOK + n) = v0;
            *(float2*)(out + ((size_t)bb * M + o + 8) * NTOK + n) = v1;
        }
    }
}

// ---------------------------------------------------------------------------
// Attention. Q/K/V tiles interleaved hi/lo float2; S 3xTF32, PV 2xTF32.
// ---------------------------------------------------------------------------
#define AS2 132    // Q/K/V row stride (float2 units)
#define PSP 136    // Ps row stride (floats)
#define ATT_SMEM (64 * AS2 * 8 * 2 + (128 * PSP + 128) * 4)

__global__ void __launch_bounds__(256) k_attn_t() {
    extern __shared__ float sm[];
    float2* Qs = (float2*)sm;             // [64 c][AS2 t] (hi,lo)
    float2* Ks = Qs + 64 * AS2;           // [64 c][AS2 s] (hi,lo), reused for V
    float*  Ps = (float*)(Ks + 64 * AS2); // [128 s][PSP t]
    float*  Ls = Ps + 128 * PSP;

    int hb = blockIdx.x >> 4, qt = blockIdx.x & 15;
    int b = hb >> 2, h = hb & 3;
    const float* qbase = g_qkv + (size_t)(b * 768 + h * 192) * NTOK;
    const float* kbase = qbase + (size_t)64 * NTOK;
    const float* vbase = qbase + (size_t)128 * NTOK;
    int tid = threadIdx.x, lane = tid & 31, wid = tid >> 5;
    int wt = wid >> 1, ws = wid & 1;
    int lq = lane >> 2, lr = lane & 3;
    int t0 = qt * 128;

    if (tid < 128) Ls[tid] = 0.f;

    // load Q (x 1/8), split, interleaved store [c][t]
#pragma unroll
    for (int r = 0; r < 8; r++) {
        int idx = tid + r * 256;
        int c = idx >> 5, t4 = (idx & 31) << 2;
        float4 v = *(const float4*)(qbase + (size_t)c * NTOK + t0 + t4);
        v.x *= 0.125f; v.y *= 0.125f; v.z *= 0.125f; v.w *= 0.125f;
        float4 hh, ll; split4(v, hh, ll);
        store_ilv((float*)(Qs + c * AS2 + t4), hh, ll);
    }

    float accO[8][4];
#pragma unroll
    for (int i = 0; i < 8; i++)
#pragma unroll
        for (int r = 0; r < 4; r++) accO[i][r] = 0.f;
    float lsum[4] = {0.f, 0.f, 0.f, 0.f};
    __syncthreads();

    for (int st = 0; st < 16; st++) {
        int s0 = st * 128;
        float4 kv[8], vv[8];
#pragma unroll
        for (int r = 0; r < 8; r++) {
            int idx = tid + r * 256;
            int c = idx >> 5, s4 = (idx & 31) << 2;
            kv[r] = *(const float4*)(kbase + (size_t)c * NTOK + s0 + s4);
            vv[r] = *(const float4*)(vbase + (size_t)c * NTOK + s0 + s4);
        }
#pragma unroll
        for (int r = 0; r < 8; r++) {
            int idx = tid + r * 256;
            int c = idx >> 5, s4 = (idx & 31) << 2;
            float4 hh, ll; split4(kv[r], hh, ll);
            store_ilv((float*)(Ks + c * AS2 + s4), hh, ll);
        }
        __syncthreads();

        // ------- phase 1: S = Q^T K (3xTF32) -------
        float accS[2][8][4];
#pragma unroll
        for (int i = 0; i < 2; i++)
#pragma unroll
            for (int j = 0; j < 8; j++)
#pragma unroll
                for (int r = 0; r < 4; r++) accS[i][j][r] = 0.f;

#pragma unroll
        for (int ks = 0; ks < 8; ks++) {
            int arow = (ks * 8 + lr) * AS2;
            uint32_t qh[2][4], ql_[2][4];
#pragma unroll
            for (int mf = 0; mf < 2; mf++) {
                int t = wt * 32 + mf * 16 + lq;
                float2 x0 = Qs[arow + t];
                float2 x1 = Qs[arow + t + 8];
                float2 x2 = Qs[arow + 4 * AS2 + t];
                float2 x3 = Qs[arow + 4 * AS2 + t + 8];
                qh[mf][0] = __float_as_uint(x0.x); ql_[mf][0] = __float_as_uint(x0.y);
                qh[mf][1] = __float_as_uint(x1.x); ql_[mf][1] = __float_as_uint(x1.y);
                qh[mf][2] = __float_as_uint(x2.x); ql_[mf][2] = __float_as_uint(x2.y);
                qh[mf][3] = __float_as_uint(x3.x); ql_[mf][3] = __float_as_uint(x3.y);
            }
#pragma unroll
            for (int nf = 0; nf < 8; nf++) {
                int s = ws * 64 + nf * 8 + lq;
                float2 y0 = Ks[arow + s];
                float2 y1 = Ks[arow + 4 * AS2 + s];
                uint32_t bh[2] = {__float_as_uint(y0.x), __float_as_uint(y1.x)};
                uint32_t bl[2] = {__float_as_uint(y0.y), __float_as_uint(y1.y)};
#pragma unroll
                for (int mf = 0; mf < 2; mf++) {
                    mma8(accS[mf][nf], qh[mf], bh);
                    mma8(accS[mf][nf], ql_[mf], bh);
                    mma8(accS[mf][nf], qh[mf], bl);
                }
            }
        }

        // exp, row sums, store P[s][t]
#pragma unroll
        for (int mf = 0; mf < 2; mf++) {
            int t = wt * 32 + mf * 16 + lq;
#pragma unroll
            for (int nf = 0; nf < 8; nf++) {
                int s = ws * 64 + nf * 8 + 2 * lr;
                float e0 = __expf(accS[mf][nf][0]);
                float e1 = __expf(accS[mf][nf][1]);
                float e2 = __expf(accS[mf][nf][2]);
                float e3 = __expf(accS[mf][nf][3]);
                lsum[mf * 2 + 0] += e0 + e1;
                lsum[mf * 2 + 1] += e2 + e3;
                Ps[s * PSP + t] = e0;
                Ps[(s + 1) * PSP + t] = e1;
                Ps[s * PSP + t + 8] = e2;
                Ps[(s + 1) * PSP + t + 8] = e3;
            }
        }
        __syncthreads();

        // store V into the K buffer
#pragma unroll
        for (int r = 0; r < 8; r++) {
            int idx = tid + r * 256;
            int c = idx >> 5, s4 = (idx & 31) << 2;
            float4 hh, ll; split4(vv[r], hh, ll);
            store_ilv((float*)(Ks + c * AS2 + s4), hh, ll);
        }
        __syncthreads();

        // ------- phase 2: O^T[t][c] += P[s][t] * V[c][s]  (2xTF32) -------
#pragma unroll
        for (int k2 = 0; k2 < 16; k2++) {
            int srow = (k2 * 8 + lr) * PSP;
            int tbase = wid * 16 + lq;
            uint32_t ph[4];
            ph[0] = f2tf(Ps[srow + tbase]);
            ph[1] = f2tf(Ps[srow + tbase + 8]);
            ph[2] = f2tf(Ps[srow + 4 * PSP + tbase]);
            ph[3] = f2tf(Ps[srow + 4 * PSP + tbase + 8]);
#pragma unroll
            for (int nf = 0; nf < 8; nf++) {
                int cc = nf * 8 + lq;
                int vb = cc * AS2 + k2 * 8 + lr;
                float2 v0 = Ks[vb];
                float2 v1 = Ks[vb + 4];
                uint32_t bh[2] = {__float_as_uint(v0.x), __float_as_uint(v1.x)};
                uint32_t bl[2] = {__float_as_uint(v0.y), __float_as_uint(v1.y)};
                mma8(accO[nf], ph, bh);
                mma8(accO[nf], ph, bl);
            }
        }
        __syncthreads();
    }

    // reduce row sums into Ls
#pragma unroll
    for (int i = 0; i < 4; i++) {
        lsum[i] += __shfl_xor_sync(0xffffffffu, lsum[i], 1);
        lsum[i] += __shfl_xor_sync(0xffffffffu, lsum[i], 2);
    }
    if (lr == 0) {
        atomicAdd(&Ls[wt * 32 + lq],          lsum[0]);
        atomicAdd(&Ls[wt * 32 + lq + 8],      lsum[1]);
        atomicAdd(&Ls[wt * 32 + 16 + lq],     lsum[2]);
        atomicAdd(&Ls[wt * 32 + 16 + lq + 8], lsum[3]);
    }
    __syncthreads();

    // normalize + transpose through Ps ([c][t]) then coalesced store
    float inv0 = 1.f / Ls[wid * 16 + lq];
    float inv1 = 1.f / Ls[wid * 16 + lq + 8];
    int t = wid * 16 + lq;
#pragma unroll
    for (int nf = 0; nf < 8; nf++) {
        int cc = nf * 8 + 2 * lr;
        Ps[cc * PSP + t]           = accO[nf][0] * inv0;
        Ps[(cc + 1) * PSP + t]     = accO[nf][1] * inv0;
        Ps[cc * PSP + t + 8]       = accO[nf][2] * inv1;
        Ps[(cc + 1) * PSP + t + 8] = accO[nf][3] * inv1;
    }
    __syncthreads();

    int rowbase = b * 256 + h * 64;
#pragma unroll
    for (int r = 0; r < 8; r++) {
        int idx = tid + r * 256;
        int c = idx >> 5, t4 = (idx & 31) << 2;
        float4 v = *(const float4*)(Ps + c * PSP + t4);
        *(float4*)(g_attn + (size_t)(rowbase + c) * NTOK + t0 + t4) = v;
    }
}

// ---------------------------------------------------------------------------
// Inverse FFT2
// ---------------------------------------------------------------------------
__global__ void __launch_bounds__(32) k_ifft(float* __restrict__ outp) {
    __shared__ float sr[32][33];
    __shared__ float si[32][33];
    __shared__ float2 tw[32];

    int img  = blockIdx.x;
    int lane = threadIdx.x;

    float sn, cs;
    __sincosf(6.283185307179586f * (float)lane / 32.f, &sn, &cs);
    tw[lane] = make_float2(cs, sn);

    const float* ip = g_proj + (size_t)img * NTOK;
#pragma unroll
    for (int y = 0; y < 32; y++) {
        sr[y][lane] = ip[(y * 32 + lane) * 2 + 0];
        si[y][lane] = ip[(y * 32 + lane) * 2 + 1];
    }
    __syncwarp();

    float cr[32], ci[32];
#pragma unroll
    for (int j = 0; j < 32; j++) { cr[j] = sr[lane][j]; ci[j] = si[lane][j]; }
    __syncwarp();

    for (int k = 0; k < 32; k++) {
        float ar = 0.f, ai = 0.f;
#pragma unroll
        for (int j = 0; j < 32; j++) {
            float2 w = tw[(j * k) & 31];
            ar += cr[j] * w.x - ci[j] * w.y;
            ai += cr[j] * w.y + ci[j] * w.x;
        }
        sr[k][lane] = ar;
        si[k][lane] = ai;
    }
    __syncwarp();

#pragma unroll
    for (int j = 0; j < 32; j++) { cr[j] = sr[lane][j]; ci[j] = si[lane][j]; }

    float* op = outp + (size_t)img * NTOK;
    for (int k = 0; k < 32; k++) {
        float ar = 0.f, ai = 0.f;
#pragma unroll
        for (int j = 0; j < 32; j++) {
            float2 w = tw[(j * k) & 31];
            ar += cr[j] * w.x - ci[j] * w.y;
            ai += cr[j] * w.y + ci[j] * w.x;
        }
        op[(k * 32 + lane) * 2 + 0] = ar * (1.f / 1024.f);
        op[(k * 32 + lane) * 2 + 1] = ai * (1.f / 1024.f);
    }
}

// ---------------------------------------------------------------------------
extern "C" void kernel_launch(void* const* d_in, const int* in_sizes, int n_in,
                              void* d_out, int out_size) {
    const float* x      = (const float*)d_in[0];
    const float* gn_w   = (const float*)d_in[1];
    const float* gn_b   = (const float*)d_in[2];
    const float* qkv_w  = (const float*)d_in[3];
    const float* qkv_b  = (const float*)d_in[4];
    const float* proj_w = (const float*)d_in[5];
    const float* proj_b = (const float*)d_in[6];
    float* out = (float*)d_out;

    float *p_xr, *p_qkv, *p_attn, *p_proj, *p_alpha, *p_bb;
    cudaGetSymbolAddress((void**)&p_xr,    g_xr);
    cudaGetSymbolAddress((void**)&p_qkv,   g_qkv);
    cudaGetSymbolAddress((void**)&p_attn,  g_attn);
    cudaGetSymbolAddress((void**)&p_proj,  g_proj);
    cudaGetSymbolAddress((void**)&p_alpha, g_alpha);
    cudaGetSymbolAddress((void**)&p_bb,    g_bb);

    cudaFuncSetAttribute(k_attn_t, cudaFuncAttributeMaxDynamicSharedMemorySize, ATT_SMEM);
    cudaFuncSetAttribute(k_gemm_t, cudaFuncAttributeMaxDynamicSharedMemorySize, GEMM_SMEM);

    k_zero_stats<<<1, 512>>>();
    k_fft<<<2048, 32>>>(x);
    k_prep_ab<<<8, 256>>>(gn_w, gn_b);
    k_prep_bb<<<768, 256>>>(qkv_w, qkv_b);
    k_gemm_t<<<dim3(16, 6, 8), 256, GEMM_SMEM>>>(qkv_w, p_xr, p_alpha, p_bb, 768, 1, p_qkv);
    k_attn_t<<<512, 256, ATT_SMEM>>>();
    k_gemm_t<<<dim3(16, 2, 8), 256, GEMM_SMEM>>>(proj_w, p_attn, nullptr, proj_b, 256, 0, p_proj);
    k_ifft<<<2048, 32>>>(out);
}

// round 6
// speedup vs baseline: 1.8958x; 1.8958x over previous
#include <cuda_runtime.h>
#include <cuda_bf16.h>
#include <cstdint>
#include <cstddef>

// ---------------------------------------------------------------------------
// FFTAttention: fft2 -> GroupNorm -> QKV gemm -> attention -> proj -> ifft2
// b=8, c=256, h=w=32, n=2048, heads=4, ch=64.
// Matmuls via bf16 m16n8k16 mma with 3-term hi/lo emulation (~2^-16 accurate).
// ---------------------------------------------------------------------------

#define NTOK 2048

__device__ float g_xr  [8 * 256 * NTOK];
__device__ float g_qkv [8 * 768 * NTOK];
__device__ float g_attn[8 * 256 * NTOK];
__device__ float g_proj[8 * 256 * NTOK];
__device__ float g_alpha[8 * 256];
__device__ float g_beta [8 * 256];
__device__ float g_bb   [8 * 768];
__device__ float g_stats[512];

// ---------------- bf16 split helpers ----------------
// hi = top-16-bit truncation of x (exact bf16), lo = bf16(x - hi).
// pack2(x0,x1): x0 -> low half (even k), x1 -> high half (odd k).
__device__ __forceinline__ void pack2(float x0, float x1, uint32_t& h, uint32_t& l) {
    uint32_t u0 = __float_as_uint(x0) & 0xFFFF0000u;
    uint32_t u1 = __float_as_uint(x1) & 0xFFFF0000u;
    h = __byte_perm(u0, u1, 0x7632);
    float r0 = x0 - __uint_as_float(u0);
    float r1 = x1 - __uint_as_float(u1);
    asm("cvt.rn.bf16x2.f32 %0, %1, %2;" : "=r"(l) : "f"(r1), "f"(r0));
}
__device__ __forceinline__ void mma16(float* d, const uint32_t* a, const uint32_t* b) {
    asm volatile(
        "mma.sync.aligned.m16n8k16.row.col.f32.bf16.bf16.f32 "
        "{%0,%1,%2,%3}, {%4,%5,%6,%7}, {%8,%9}, {%0,%1,%2,%3};\n"
        : "+f"(d[0]), "+f"(d[1]), "+f"(d[2]), "+f"(d[3])
        : "r"(a[0]), "r"(a[1]), "r"(a[2]), "r"(a[3]), "r"(b[0]), "r"(b[1]));
}

__global__ void k_zero_stats() { g_stats[threadIdx.x] = 0.f; }

// ---------------------------------------------------------------------------
// Forward FFT2 + groupnorm stats (one warp per (b,c) image)
// ---------------------------------------------------------------------------
__global__ void __launch_bounds__(32) k_fft(const float* __restrict__ x) {
    __shared__ float sr[32][33];
    __shared__ float si[32][33];
    __shared__ float2 tw[32];

    int img  = blockIdx.x;
    int lane = threadIdx.x;

    float sn, cs;
    __sincosf(-6.283185307179586f * (float)lane / 32.f, &sn, &cs);
    tw[lane] = make_float2(cs, sn);

    const float* xin = x + (size_t)img * 1024;
#pragma unroll
    for (int y = 0; y < 32; y++) sr[y][lane] = xin[y * 32 + lane];
    __syncwarp();

    float vr[32];
#pragma unroll
    for (int j = 0; j < 32; j++) vr[j] = sr[lane][j];
    __syncwarp();

    for (int k = 0; k < 32; k++) {
        float ar = 0.f, ai = 0.f;
#pragma unroll
        for (int j = 0; j < 32; j++) {
            float2 w = tw[(j * k) & 31];
            ar += vr[j] * w.x;
            ai += vr[j] * w.y;
        }
        sr[k][lane] = ar;
        si[k][lane] = ai;
    }
    __syncwarp();

    float cr[32], ci[32];
#pragma unroll
    for (int t = 0; t < 32; t++) { cr[t] = sr[lane][t]; ci[t] = si[lane][t]; }

    float* outp = g_xr + (size_t)img * NTOK;
    float sum = 0.f, ssq = 0.f;
    for (int k = 0; k < 32; k++) {
        float ar = 0.f, ai = 0.f;
#pragma unroll
        for (int j = 0; j < 32; j++) {
            float2 w = tw[(j * k) & 31];
            ar += cr[j] * w.x - ci[j] * w.y;
            ai += cr[j] * w.y + ci[j] * w.x;
        }
        outp[(k * 32 + lane) * 2 + 0] = ar;
        outp[(k * 32 + lane) * 2 + 1] = ai;
        sum += ar + ai;
        ssq += ar * ar + ai * ai;
    }

#pragma unroll
    for (int off = 16; off > 0; off >>= 1) {
        sum += __shfl_xor_sync(0xffffffffu, sum, off);
        ssq += __shfl_xor_sync(0xffffffffu, ssq, off);
    }
    if (lane == 0) {
        int b  = img >> 8;
        int ch = img & 255;
        int grp = b * 32 + (ch >> 3);
        atomicAdd(&g_stats[grp * 2 + 0], sum);
        atomicAdd(&g_stats[grp * 2 + 1], ssq);
    }
}

__global__ void k_prep_ab(const float* __restrict__ gn_w, const float* __restrict__ gn_b) {
    int b = blockIdx.x;
    int c = threadIdx.x;
    int grp = b * 32 + (c >> 3);
    float s0 = g_stats[grp * 2 + 0];
    float s1 = g_stats[grp * 2 + 1];
    float mean = s0 * (1.f / 16384.f);
    float var  = s1 * (1.f / 16384.f) - mean * mean;
    float rs   = rsqrtf(var + 1e-5f);
    float w = gn_w[c];
    g_alpha[b * 256 + c] = rs * w;
    g_beta [b * 256 + c] = gn_b[c] - mean * rs * w;
}

__global__ void __launch_bounds__(256) k_prep_bb(const float* __restrict__ qkv_w,
                                                 const float* __restrict__ qkv_b) {
    int w = (blockIdx.x * 256 + threadIdx.x) >> 5;
    int lane = threadIdx.x & 31;
    int b = w / 768, o = w - b * 768;
    const float* wr = qkv_w + (size_t)o * 256;
    const float* be = g_beta + b * 256;
    float acc = 0.f;
#pragma unroll
    for (int c = lane; c < 256; c += 32) acc += wr[c] * be[c];
#pragma unroll
    for (int off = 16; off > 0; off >>= 1) acc += __shfl_xor_sync(0xffffffffu, acc, off);
    if (lane == 0) g_bb[w] = acc + qkv_b[o];
}

// ---------------------------------------------------------------------------
// bf16-3x GEMM: out[b][o][n] = bias + sum_c A[o][c]*(alpha[b][c])*X[b][c][n]
// block 128x128, K-chunk 32 (16 c-pairs), 8 warps (2x4), warp 64x32.
// ---------------------------------------------------------------------------
#define GAS 20     // A tile stride, uint32 units (16 pairs + pad)
#define GBS 136    // B tile stride, uint32 units (128 n + pad)
#define GEMM_SMEM ((2 * 128 * GAS + 2 * 16 * GBS) * 4)

__global__ void __launch_bounds__(256, 2) k_gemm_b(
    const float* __restrict__ A, const float* __restrict__ X,
    const float* __restrict__ alpha, const float* __restrict__ bias,
    int M, int biasPerBatch, float* __restrict__ out)
{
    extern __shared__ uint32_t sg[];
    uint32_t* ApH = sg;                  // [128 m][GAS] packed c-pairs
    uint32_t* ApL = ApH + 128 * GAS;
    uint32_t* BpH = ApL + 128 * GAS;     // [16 c2][GBS]
    uint32_t* BpL = BpH + 16 * GBS;

    int n0 = blockIdx.x * 128, o0 = blockIdx.y * 128, bb = blockIdx.z;
    int tid = threadIdx.x, lane = tid & 31, wid = tid >> 5;
    int wm = wid >> 2, wn = wid & 3;
    int lq = lane >> 2, lr = lane & 3;
    const float* Xb = X + (size_t)bb * 256 * NTOK;
    bool useAlpha = (alpha != nullptr);

    float acc[4][4][4];
#pragma unroll
    for (int i = 0; i < 4; i++)
#pragma unroll
        for (int j = 0; j < 4; j++)
#pragma unroll
            for (int r = 0; r < 4; r++) acc[i][j][r] = 0.f;

    for (int k0 = 0; k0 < 256; k0 += 32) {
        __syncthreads();
        // A tile: rows o0..o0+127, 32 c packed into 16 pairs
#pragma unroll
        for (int r = 0; r < 2; r++) {
            int idx = tid + r * 256;
            int row = idx >> 2, cq = idx & 3;          // cq: group of 8 c
            const float* ap = A + (size_t)(o0 + row) * 256 + k0 + cq * 8;
            float4 v0 = *(const float4*)(ap);
            float4 v1 = *(const float4*)(ap + 4);
            uint32_t h[4], l[4];
            pack2(v0.x, v0.y, h[0], l[0]);
            pack2(v0.z, v0.w, h[1], l[1]);
            pack2(v1.x, v1.y, h[2], l[2]);
            pack2(v1.z, v1.w, h[3], l[3]);
            *(uint4*)(ApH + row * GAS + cq * 4) = make_uint4(h[0], h[1], h[2], h[3]);
            *(uint4*)(ApL + row * GAS + cq * 4) = make_uint4(l[0], l[1], l[2], l[3]);
        }
        // B tile: pairs along c (two adjacent c rows)
#pragma unroll
        for (int r = 0; r < 2; r++) {
            int idx = tid + r * 256;
            int c2 = idx >> 5, n4 = (idx & 31) << 2;
            const float* xp = Xb + (size_t)(k0 + 2 * c2) * NTOK + n0 + n4;
            float4 x0 = *(const float4*)(xp);
            float4 x1 = *(const float4*)(xp + NTOK);
            if (useAlpha) {
                float a0 = alpha[bb * 256 + k0 + 2 * c2];
                float a1 = alpha[bb * 256 + k0 + 2 * c2 + 1];
                x0.x *= a0; x0.y *= a0; x0.z *= a0; x0.w *= a0;
                x1.x *= a1; x1.y *= a1; x1.z *= a1; x1.w *= a1;
            }
            uint32_t h[4], l[4];
            pack2(x0.x, x1.x, h[0], l[0]);
            pack2(x0.y, x1.y, h[1], l[1]);
            pack2(x0.z, x1.z, h[2], l[2]);
            pack2(x0.w, x1.w, h[3], l[3]);
            *(uint4*)(BpH + c2 * GBS + n4) = make_uint4(h[0], h[1], h[2], h[3]);
            *(uint4*)(BpL + c2 * GBS + n4) = make_uint4(l[0], l[1], l[2], l[3]);
        }
        __syncthreads();

#pragma unroll
        for (int ks = 0; ks < 2; ks++) {
            uint32_t ah[4][4], al_[4][4];
#pragma unroll
            for (int mf = 0; mf < 4; mf++) {
                int m = wm * 64 + mf * 16 + lq;
                int r0 = m * GAS + ks * 8 + lr;
                int r1 = r0 + 4;
                ah[mf][0] = ApH[r0]; ah[mf][1] = ApH[r0 + 8 * GAS];
                ah[mf][2] = ApH[r1]; ah[mf][3] = ApH[r1 + 8 * GAS];
                al_[mf][0] = ApL[r0]; al_[mf][1] = ApL[r0 + 8 * GAS];
                al_[mf][2] = ApL[r1]; al_[mf][3] = ApL[r1 + 8 * GAS];
            }
#pragma unroll
            for (int nf = 0; nf < 4; nf++) {
                int n = wn * 32 + nf * 8 + lq;
                int b0i = (ks * 8 + lr) * GBS + n;
                int b1i = (ks * 8 + 4 + lr) * GBS + n;
                uint32_t bh[2] = {BpH[b0i], BpH[b1i]};
                uint32_t bl[2] = {BpL[b0i], BpL[b1i]};
#pragma unroll
                for (int mf = 0; mf < 4; mf++) {
                    mma16(acc[mf][nf], ah[mf], bh);
                    mma16(acc[mf][nf], al_[mf], bh);
                    mma16(acc[mf][nf], ah[mf], bl);
                }
            }
        }
    }

#pragma unroll
    for (int mf = 0; mf < 4; mf++) {
        int o = o0 + wm * 64 + mf * 16 + lq;
        float b0 = biasPerBatch ? bias[bb * M + o] : bias[o];
        float b1 = biasPerBatch ? bias[bb * M + o + 8] : bias[o + 8];
#pragma unroll
        for (int nf = 0; nf < 4; nf++) {
            int n = n0 + wn * 32 + nf * 8 + 2 * lr;
            float2 v0 = make_float2(acc[mf][nf][0] + b0, acc[mf][nf][1] + b0);
            float2 v1 = make_float2(acc[mf][nf][2] + b1, acc[mf][nf][3] + b1);
            *(float2*)(out + ((size_t)bb * M + o) * NTOK + n) = v0;
            *(float2*)(out + ((size_t)bb * M + o + 8) * NTOK + n) = v1;
        }
    }
}

// ---------------------------------------------------------------------------
// Attention (bf16-3x). Block = (head-batch, 128-q tile), 8 warps.
// S = Q^T K (3x bf16), P = exp(S) packed bf16 pairs, O^T = P V (3x bf16).
// ---------------------------------------------------------------------------
#define QKS 136    // Qp/Kp stride (uint32), rows = c2 (32)
#define VS2 68     // Vp stride (uint32), rows = c (64)
#define PS2 68     // Ps stride (uint32), rows = t (128)
#define PFP 136    // float-view stride for final transpose
#define ATT_SMEM ((4 * 32 * QKS + 2 * 64 * VS2 + 2 * 128 * PS2) * 4 + 512)

__global__ void __launch_bounds__(256) k_attn_b() {
    extern __shared__ uint32_t su[];
    uint32_t* QpH = su;                    // [32 c2][QKS t]
    uint32_t* QpL = QpH + 32 * QKS;
    uint32_t* KpH = QpL + 32 * QKS;        // [32 c2][QKS s]
    uint32_t* KpL = KpH + 32 * QKS;
    uint32_t* VpH = KpL + 32 * QKS;        // [64 c][VS2 s2]
    uint32_t* VpL = VpH + 64 * VS2;
    uint32_t* PsH = VpL + 64 * VS2;        // [128 t][PS2 s2]
    uint32_t* PsL = PsH + 128 * PS2;
    float*    Ls  = (float*)(PsL + 128 * PS2);

    int hb = blockIdx.x >> 4, qt = blockIdx.x & 15;
    int b = hb >> 2, h = hb & 3;
    const float* qbase = g_qkv + (size_t)(b * 768 + h * 192) * NTOK;
    const float* kbase = qbase + (size_t)64 * NTOK;
    const float* vbase = qbase + (size_t)128 * NTOK;
    int tid = threadIdx.x, lane = tid & 31, wid = tid >> 5;
    int wt = wid >> 1, ws = wid & 1;
    int lq = lane >> 2, lr = lane & 3;
    int t0 = qt * 128;

    if (tid < 128) Ls[tid] = 0.f;

    // Q tile: pairs along c, scaled by 1/8
#pragma unroll
    for (int r = 0; r < 4; r++) {
        int idx = tid + r * 256;
        int c2 = idx >> 5, t4 = (idx & 31) << 2;
        const float* qp = qbase + (size_t)(2 * c2) * NTOK + t0 + t4;
        float4 q0 = *(const float4*)(qp);
        float4 q1 = *(const float4*)(qp + NTOK);
        q0.x *= 0.125f; q0.y *= 0.125f; q0.z *= 0.125f; q0.w *= 0.125f;
        q1.x *= 0.125f; q1.y *= 0.125f; q1.z *= 0.125f; q1.w *= 0.125f;
        uint32_t hh[4], ll[4];
        pack2(q0.x, q1.x, hh[0], ll[0]);
        pack2(q0.y, q1.y, hh[1], ll[1]);
        pack2(q0.z, q1.z, hh[2], ll[2]);
        pack2(q0.w, q1.w, hh[3], ll[3]);
        *(uint4*)(QpH + c2 * QKS + t4) = make_uint4(hh[0], hh[1], hh[2], hh[3]);
        *(uint4*)(QpL + c2 * QKS + t4) = make_uint4(ll[0], ll[1], ll[2], ll[3]);
    }

    float accO[8][4];
#pragma unroll
    for (int i = 0; i < 8; i++)
#pragma unroll
        for (int r = 0; r < 4; r++) accO[i][r] = 0.f;
    float lsum[4] = {0.f, 0.f, 0.f, 0.f};

    for (int st = 0; st < 16; st++) {
        int s0 = st * 128;
        // K tile: pairs along c
#pragma unroll
        for (int r = 0; r < 4; r++) {
            int idx = tid + r * 256;
            int c2 = idx >> 5, s4 = (idx & 31) << 2;
            const float* kp = kbase + (size_t)(2 * c2) * NTOK + s0 + s4;
            float4 k0v = *(const float4*)(kp);
            float4 k1v = *(const float4*)(kp + NTOK);
            uint32_t hh[4], ll[4];
            pack2(k0v.x, k1v.x, hh[0], ll[0]);
            pack2(k0v.y, k1v.y, hh[1], ll[1]);
            pack2(k0v.z, k1v.z, hh[2], ll[2]);
            pack2(k0v.w, k1v.w, hh[3], ll[3]);
            *(uint4*)(KpH + c2 * QKS + s4) = make_uint4(hh[0], hh[1], hh[2], hh[3]);
            *(uint4*)(KpL + c2 * QKS + s4) = make_uint4(ll[0], ll[1], ll[2], ll[3]);
        }
        // V tile: natural pairs along s
#pragma unroll
        for (int r = 0; r < 8; r++) {
            int idx = tid + r * 256;
            int c = idx >> 5, sg = idx & 31;
            const float* vp = vbase + (size_t)c * NTOK + s0 + sg * 4;
            float4 v = *(const float4*)(vp);
            uint32_t h0, l0, h1, l1;
            pack2(v.x, v.y, h0, l0);
            pack2(v.z, v.w, h1, l1);
            *(uint2*)(VpH + c * VS2 + sg * 2) = make_uint2(h0, h1);
            *(uint2*)(VpL + c * VS2 + sg * 2) = make_uint2(l0, l1);
        }
        __syncthreads();

        // ------- phase 1: S = Q^T K -------
        float accS[2][8][4];
#pragma unroll
        for (int i = 0; i < 2; i++)
#pragma unroll
            for (int j = 0; j < 8; j++)
#pragma unroll
                for (int r = 0; r < 4; r++) accS[i][j][r] = 0.f;

#pragma unroll
        for (int ks = 0; ks < 4; ks++) {
            uint32_t ah[2][4], al_[2][4];
#pragma unroll
            for (int mf = 0; mf < 2; mf++) {
                int t = wt * 32 + mf * 16 + lq;
                int r0 = (ks * 8 + lr) * QKS + t;
                int r1 = (ks * 8 + 4 + lr) * QKS + t;
                ah[mf][0] = QpH[r0]; ah[mf][1] = QpH[r0 + 8];
                ah[mf][2] = QpH[r1]; ah[mf][3] = QpH[r1 + 8];
                al_[mf][0] = QpL[r0]; al_[mf][1] = QpL[r0 + 8];
                al_[mf][2] = QpL[r1]; al_[mf][3] = QpL[r1 + 8];
            }
#pragma unroll
            for (int nf = 0; nf < 8; nf++) {
                int s = ws * 64 + nf * 8 + lq;
                int b0i = (ks * 8 + lr) * QKS + s;
                int b1i = (ks * 8 + 4 + lr) * QKS + s;
                uint32_t bh[2] = {KpH[b0i], KpH[b1i]};
                uint32_t bl[2] = {KpL[b0i], KpL[b1i]};
#pragma unroll
                for (int mf = 0; mf < 2; mf++) {
                    mma16(accS[mf][nf], ah[mf], bh);
                    mma16(accS[mf][nf], al_[mf], bh);
                    mma16(accS[mf][nf], ah[mf], bl);
                }
            }
        }

        // exp, row sums, pack P pairs along s
#pragma unroll
        for (int mf = 0; mf < 2; mf++) {
            int t = wt * 32 + mf * 16 + lq;
#pragma unroll
            for (int nf = 0; nf < 8; nf++) {
                int s2 = ws * 32 + nf * 4 + lr;
                float e0 = __expf(accS[mf][nf][0]);
                float e1 = __expf(accS[mf][nf][1]);
                float e2 = __expf(accS[mf][nf][2]);
                float e3 = __expf(accS[mf][nf][3]);
                lsum[mf * 2 + 0] += e0 + e1;
                lsum[mf * 2 + 1] += e2 + e3;
                uint32_t h01, l01, h23, l23;
                pack2(e0, e1, h01, l01);
                pack2(e2, e3, h23, l23);
                PsH[t * PS2 + s2] = h01;       PsL[t * PS2 + s2] = l01;
                PsH[(t + 8) * PS2 + s2] = h23; PsL[(t + 8) * PS2 + s2] = l23;
            }
        }
        __syncthreads();

        // ------- phase 2: O^T[t][c] += P[t][s] * V[c][s] -------
        int tb = wid * 16 + lq;
#pragma unroll
        for (int ks = 0; ks < 8; ks++) {
            int p0 = tb * PS2 + ks * 8 + lr;
            uint32_t ah[4], al_[4];
            ah[0] = PsH[p0];            ah[1] = PsH[p0 + 8 * PS2];
            ah[2] = PsH[p0 + 4];        ah[3] = PsH[p0 + 8 * PS2 + 4];
            al_[0] = PsL[p0];           al_[1] = PsL[p0 + 8 * PS2];
            al_[2] = PsL[p0 + 4];       al_[3] = PsL[p0 + 8 * PS2 + 4];
#pragma unroll
            for (int nf = 0; nf < 8; nf++) {
                int c = nf * 8 + lq;
                int b0i = c * VS2 + ks * 8 + lr;
                uint32_t bh[2] = {VpH[b0i], VpH[b0i + 4]};
                uint32_t bl[2] = {VpL[b0i], VpL[b0i + 4]};
                mma16(accO[nf], ah, bh);
                mma16(accO[nf], al_, bh);
                mma16(accO[nf], ah, bl);
            }
        }
        __syncthreads();
    }

    // reduce row sums into Ls
#pragma unroll
    for (int i = 0; i < 4; i++) {
        lsum[i] += __shfl_xor_sync(0xffffffffu, lsum[i], 1);
        lsum[i] += __shfl_xor_sync(0xffffffffu, lsum[i], 2);
    }
    if (lr == 0) {
        atomicAdd(&Ls[wt * 32 + lq],          lsum[0]);
        atomicAdd(&Ls[wt * 32 + lq + 8],      lsum[1]);
        atomicAdd(&Ls[wt * 32 + 16 + lq],     lsum[2]);
        atomicAdd(&Ls[wt * 32 + 16 + lq + 8], lsum[3]);
    }
    __syncthreads();

    // normalize + transpose via float scratch (overwrites Q/K tiles)
    float* Pf = (float*)su;    // [64 c][PFP t]
    float inv0 = 1.f / Ls[wid * 16 + lq];
    float inv1 = 1.f / Ls[wid * 16 + lq + 8];
    int t = wid * 16 + lq;
#pragma unroll
    for (int nf = 0; nf < 8; nf++) {
        int cc = nf * 8 + 2 * lr;
        Pf[cc * PFP + t]           = accO[nf][0] * inv0;
        Pf[(cc + 1) * PFP + t]     = accO[nf][1] * inv0;
        Pf[cc * PFP + t + 8]       = accO[nf][2] * inv1;
        Pf[(cc + 1) * PFP + t + 8] = accO[nf][3] * inv1;
    }
    __syncthreads();

    int rowbase = b * 256 + h * 64;
#pragma unroll
    for (int r = 0; r < 8; r++) {
        int idx = tid + r * 256;
        int c = idx >> 5, t4 = (idx & 31) << 2;
        float4 v = *(const float4*)(Pf + c * PFP + t4);
        *(float4*)(g_attn + (size_t)(rowbase + c) * NTOK + t0 + t4) = v;
    }
}

// ---------------------------------------------------------------------------
// Inverse FFT2
// ---------------------------------------------------------------------------
__global__ void __launch_bounds__(32) k_ifft(float* __restrict__ outp) {
    __shared__ float sr[32][33];
    __shared__ float si[32][33];
    __shared__ float2 tw[32];

    int img  = blockIdx.x;
    int lane = threadIdx.x;

    float sn, cs;
    __sincosf(6.283185307179586f * (float)lane / 32.f, &sn, &cs);
    tw[lane] = make_float2(cs, sn);

    const float* ip = g_proj + (size_t)img * NTOK;
#pragma unroll
    for (int y = 0; y < 32; y++) {
        sr[y][lane] = ip[(y * 32 + lane) * 2 + 0];
        si[y][lane] = ip[(y * 32 + lane) * 2 + 1];
    }
    __syncwarp();

    float cr[32], ci[32];
#pragma unroll
    for (int j = 0; j < 32; j++) { cr[j] = sr[lane][j]; ci[j] = si[lane][j]; }
    __syncwarp();

    for (int k = 0; k < 32; k++) {
        float ar = 0.f, ai = 0.f;
#pragma unroll
        for (int j = 0; j < 32; j++) {
            float2 w = tw[(j * k) & 31];
            ar += cr[j] * w.x - ci[j] * w.y;
            ai += cr[j] * w.y + ci[j] * w.x;
        }
        sr[k][lane] = ar;
        si[k][lane] = ai;
    }
    __syncwarp();

#pragma unroll
    for (int j = 0; j < 32; j++) { cr[j] = sr[lane][j]; ci[j] = si[lane][j]; }

    float* op = outp + (size_t)img * NTOK;
    for (int k = 0; k < 32; k++) {
        float ar = 0.f, ai = 0.f;
#pragma unroll
        for (int j = 0; j < 32; j++) {
            float2 w = tw[(j * k) & 31];
            ar += cr[j] * w.x - ci[j] * w.y;
            ai += cr[j] * w.y + ci[j] * w.x;
        }
        op[(k * 32 + lane) * 2 + 0] = ar * (1.f / 1024.f);
        op[(k * 32 + lane) * 2 + 1] = ai * (1.f / 1024.f);
    }
}

// ---------------------------------------------------------------------------
extern "C" void kernel_launch(void* const* d_in, const int* in_sizes, int n_in,
                              void* d_out, int out_size) {
    const float* x      = (const float*)d_in[0];
    const float* gn_w   = (const float*)d_in[1];
    const float* gn_b   = (const float*)d_in[2];
    const float* qkv_w  = (const float*)d_in[3];
    const float* qkv_b  = (const float*)d_in[4];
    const float* proj_w = (const float*)d_in[5];
    const float* proj_b = (const float*)d_in[6];
    float* out = (float*)d_out;

    float *p_xr, *p_qkv, *p_attn, *p_proj, *p_alpha, *p_bb;
    cudaGetSymbolAddress((void**)&p_xr,    g_xr);
    cudaGetSymbolAddress((void**)&p_qkv,   g_qkv);
    cudaGetSymbolAddress((void**)&p_attn,  g_attn);
    cudaGetSymbolAddress((void**)&p_proj,  g_proj);
    cudaGetSymbolAddress((void**)&p_alpha, g_alpha);
    cudaGetSymbolAddress((void**)&p_bb,    g_bb);

    cudaFuncSetAttribute(k_attn_b, cudaFuncAttributeMaxDynamicSharedMemorySize, ATT_SMEM);
    cudaFuncSetAttribute(k_gemm_b, cudaFuncAttributeMaxDynamicSharedMemorySize, GEMM_SMEM);

    k_zero_stats<<<1, 512>>>();
    k_fft<<<2048, 32>>>(x);
    k_prep_ab<<<8, 256>>>(gn_w, gn_b);
    k_prep_bb<<<768, 256>>>(qkv_w, qkv_b);
    k_gemm_b<<<dim3(16, 6, 8), 256, GEMM_SMEM>>>(qkv_w, p_xr, p_alpha, p_bb, 768, 1, p_qkv);
    k_attn_b<<<512, 256, ATT_SMEM>>>();
    k_gemm_b<<<dim3(16, 2, 8), 256, GEMM_SMEM>>>(proj_w, p_attn, nullptr, proj_b, 256, 0, p_proj);
    k_ifft<<<2048, 32>>>(out);
}

// round 7
// speedup vs baseline: 2.0867x; 1.1007x over previous
#include <cuda_runtime.h>
#include <cuda_fp16.h>
#include <cstdint>
#include <cstddef>

// ---------------------------------------------------------------------------
// FFTAttention: fft2 -> GroupNorm -> QKV gemm -> attention -> proj -> ifft2
// b=8, c=256, h=w=32, n=2048, heads=4, ch=64.
// Matmuls via fp16 m16n8k16 mma, hi/lo 3-term emulation (~2^-22);
// PV uses unsplit fp16 P (2 MMAs).
// ---------------------------------------------------------------------------

#define NTOK 2048

__device__ float g_xr  [8 * 256 * NTOK];
__device__ float g_qkv [8 * 768 * NTOK];
__device__ float g_attn[8 * 256 * NTOK];
__device__ float g_proj[8 * 256 * NTOK];
__device__ float g_alpha[8 * 256];
__device__ float g_beta [8 * 256];
__device__ float g_bb   [8 * 768];
__device__ float g_stats[512];

// ---------------- fp16 split helpers ----------------
// pack_h(x0,x1): f16x2 with x0 in low half (even k), x1 in high half (odd k).
__device__ __forceinline__ uint32_t pack_h(float x0, float x1) {
    uint32_t h;
    asm("cvt.rn.f16x2.f32 %0, %1, %2;" : "=r"(h) : "f"(x1), "f"(x0));
    return h;
}
// hi = fp16(x) (rn), lo = fp16(x - hi); ~22 mantissa bits combined.
__device__ __forceinline__ void pack2(float x0, float x1, uint32_t& h, uint32_t& l) {
    asm("cvt.rn.f16x2.f32 %0, %1, %2;" : "=r"(h) : "f"(x1), "f"(x0));
    __half2 hh = *reinterpret_cast<const __half2*>(&h);
    float r0 = x0 - __low2float(hh);
    float r1 = x1 - __high2float(hh);
    asm("cvt.rn.f16x2.f32 %0, %1, %2;" : "=r"(l) : "f"(r1), "f"(r0));
}
__device__ __forceinline__ void mma16(float* d, const uint32_t* a, const uint32_t* b) {
    asm volatile(
        "mma.sync.aligned.m16n8k16.row.col.f32.f16.f16.f32 "
        "{%0,%1,%2,%3}, {%4,%5,%6,%7}, {%8,%9}, {%0,%1,%2,%3};\n"
        : "+f"(d[0]), "+f"(d[1]), "+f"(d[2]), "+f"(d[3])
        : "r"(a[0]), "r"(a[1]), "r"(a[2]), "r"(a[3]), "r"(b[0]), "r"(b[1]));
}

__global__ void k_zero_stats() { g_stats[threadIdx.x] = 0.f; }

// ---------------------------------------------------------------------------
// Forward FFT2 + groupnorm stats (one warp per (b,c) image)
// ---------------------------------------------------------------------------
__global__ void __launch_bounds__(32) k_fft(const float* __restrict__ x) {
    __shared__ float sr[32][33];
    __shared__ float si[32][33];
    __shared__ float2 tw[32];

    int img  = blockIdx.x;
    int lane = threadIdx.x;

    float sn, cs;
    __sincosf(-6.283185307179586f * (float)lane / 32.f, &sn, &cs);
    tw[lane] = make_float2(cs, sn);

    const float* xin = x + (size_t)img * 1024;
#pragma unroll
    for (int y = 0; y < 32; y++) sr[y][lane] = xin[y * 32 + lane];
    __syncwarp();

    float vr[32];
#pragma unroll
    for (int j = 0; j < 32; j++) vr[j] = sr[lane][j];
    __syncwarp();

    for (int k = 0; k < 32; k++) {
        float ar = 0.f, ai = 0.f;
#pragma unroll
        for (int j = 0; j < 32; j++) {
            float2 w = tw[(j * k) & 31];
            ar += vr[j] * w.x;
            ai += vr[j] * w.y;
        }
        sr[k][lane] = ar;
        si[k][lane] = ai;
    }
    __syncwarp();

    float cr[32], ci[32];
#pragma unroll
    for (int t = 0; t < 32; t++) { cr[t] = sr[lane][t]; ci[t] = si[lane][t]; }

    float* outp = g_xr + (size_t)img * NTOK;
    float sum = 0.f, ssq = 0.f;
    for (int k = 0; k < 32; k++) {
        float ar = 0.f, ai = 0.f;
#pragma unroll
        for (int j = 0; j < 32; j++) {
            float2 w = tw[(j * k) & 31];
            ar += cr[j] * w.x - ci[j] * w.y;
            ai += cr[j] * w.y + ci[j] * w.x;
        }
        outp[(k * 32 + lane) * 2 + 0] = ar;
        outp[(k * 32 + lane) * 2 + 1] = ai;
        sum += ar + ai;
        ssq += ar * ar + ai * ai;
    }

#pragma unroll
    for (int off = 16; off > 0; off >>= 1) {
        sum += __shfl_xor_sync(0xffffffffu, sum, off);
        ssq += __shfl_xor_sync(0xffffffffu, ssq, off);
    }
    if (lane == 0) {
        int b  = img >> 8;
        int ch = img & 255;
        int grp = b * 32 + (ch >> 3);
        atomicAdd(&g_stats[grp * 2 + 0], sum);
        atomicAdd(&g_stats[grp * 2 + 1], ssq);
    }
}

__global__ void k_prep_ab(const float* __restrict__ gn_w, const float* __restrict__ gn_b) {
    int b = blockIdx.x;
    int c = threadIdx.x;
    int grp = b * 32 + (c >> 3);
    float s0 = g_stats[grp * 2 + 0];
    float s1 = g_stats[grp * 2 + 1];
    float mean = s0 * (1.f / 16384.f);
    float var  = s1 * (1.f / 16384.f) - mean * mean;
    float rs   = rsqrtf(var + 1e-5f);
    float w = gn_w[c];
    g_alpha[b * 256 + c] = rs * w;
    g_beta [b * 256 + c] = gn_b[c] - mean * rs * w;
}

__global__ void __launch_bounds__(256) k_prep_bb(const float* __restrict__ qkv_w,
                                                 const float* __restrict__ qkv_b) {
    int w = (blockIdx.x * 256 + threadIdx.x) >> 5;
    int lane = threadIdx.x & 31;
    int b = w / 768, o = w - b * 768;
    const float* wr = qkv_w + (size_t)o * 256;
    const float* be = g_beta + b * 256;
    float acc = 0.f;
#pragma unroll
    for (int c = lane; c < 256; c += 32) acc += wr[c] * be[c];
#pragma unroll
    for (int off = 16; off > 0; off >>= 1) acc += __shfl_xor_sync(0xffffffffu, acc, off);
    if (lane == 0) g_bb[w] = acc + qkv_b[o];
}

// ---------------------------------------------------------------------------
// fp16-3x GEMM: out[b][o][n] = bias + sum_c A[o][c]*(alpha[b][c])*X[b][c][n]
// block 128x128, K-chunk 32 (16 c-pairs), 8 warps (2x4), warp 64x32.
// ---------------------------------------------------------------------------
#define GAS 20     // A tile stride, uint32 units (16 pairs + pad)
#define GBS 136    // B tile stride, uint32 units (128 n + pad)
#define GEMM_SMEM ((2 * 128 * GAS + 2 * 16 * GBS) * 4)

__global__ void __launch_bounds__(256, 2) k_gemm_b(
    const float* __restrict__ A, const float* __restrict__ X,
    const float* __restrict__ alpha, const float* __restrict__ bias,
    int M, int biasPerBatch, float* __restrict__ out)
{
    extern __shared__ uint32_t sg[];
    uint32_t* ApH = sg;                  // [128 m][GAS] packed c-pairs
    uint32_t* ApL = ApH + 128 * GAS;
    uint32_t* BpH = ApL + 128 * GAS;     // [16 c2][GBS]
    uint32_t* BpL = BpH + 16 * GBS;

    int n0 = blockIdx.x * 128, o0 = blockIdx.y * 128, bb = blockIdx.z;
    int tid = threadIdx.x, lane = tid & 31, wid = tid >> 5;
    int wm = wid >> 2, wn = wid & 3;
    int lq = lane >> 2, lr = lane & 3;
    const float* Xb = X + (size_t)bb * 256 * NTOK;
    bool useAlpha = (alpha != nullptr);

    float acc[4][4][4];
#pragma unroll
    for (int i = 0; i < 4; i++)
#pragma unroll
        for (int j = 0; j < 4; j++)
#pragma unroll
            for (int r = 0; r < 4; r++) acc[i][j][r] = 0.f;

    for (int k0 = 0; k0 < 256; k0 += 32) {
        __syncthreads();
        // A tile: rows o0..o0+127, 32 c packed into 16 pairs
#pragma unroll
        for (int r = 0; r < 2; r++) {
            int idx = tid + r * 256;
            int row = idx >> 2, cq = idx & 3;
            const float* ap = A + (size_t)(o0 + row) * 256 + k0 + cq * 8;
            float4 v0 = *(const float4*)(ap);
            float4 v1 = *(const float4*)(ap + 4);
            uint32_t h[4], l[4];
            pack2(v0.x, v0.y, h[0], l[0]);
            pack2(v0.z, v0.w, h[1], l[1]);
            pack2(v1.x, v1.y, h[2], l[2]);
            pack2(v1.z, v1.w, h[3], l[3]);
            *(uint4*)(ApH + row * GAS + cq * 4) = make_uint4(h[0], h[1], h[2], h[3]);
            *(uint4*)(ApL + row * GAS + cq * 4) = make_uint4(l[0], l[1], l[2], l[3]);
        }
        // B tile: pairs along c (two adjacent c rows)
#pragma unroll
        for (int r = 0; r < 2; r++) {
            int idx = tid + r * 256;
            int c2 = idx >> 5, n4 = (idx & 31) << 2;
            const float* xp = Xb + (size_t)(k0 + 2 * c2) * NTOK + n0 + n4;
            float4 x0 = *(const float4*)(xp);
            float4 x1 = *(const float4*)(xp + NTOK);
            if (useAlpha) {
                float a0 = alpha[bb * 256 + k0 + 2 * c2];
                float a1 = alpha[bb * 256 + k0 + 2 * c2 + 1];
                x0.x *= a0; x0.y *= a0; x0.z *= a0; x0.w *= a0;
                x1.x *= a1; x1.y *= a1; x1.z *= a1; x1.w *= a1;
            }
            uint32_t h[4], l[4];
            pack2(x0.x, x1.x, h[0], l[0]);
            pack2(x0.y, x1.y, h[1], l[1]);
            pack2(x0.z, x1.z, h[2], l[2]);
            pack2(x0.w, x1.w, h[3], l[3]);
            *(uint4*)(BpH + c2 * GBS + n4) = make_uint4(h[0], h[1], h[2], h[3]);
            *(uint4*)(BpL + c2 * GBS + n4) = make_uint4(l[0], l[1], l[2], l[3]);
        }
        __syncthreads();

#pragma unroll
        for (int ks = 0; ks < 2; ks++) {
            uint32_t ah[4][4], al_[4][4];
#pragma unroll
            for (int mf = 0; mf < 4; mf++) {
                int m = wm * 64 + mf * 16 + lq;
                int r0 = m * GAS + ks * 8 + lr;
                int r1 = r0 + 4;
                ah[mf][0] = ApH[r0]; ah[mf][1] = ApH[r0 + 8 * GAS];
                ah[mf][2] = ApH[r1]; ah[mf][3] = ApH[r1 + 8 * GAS];
                al_[mf][0] = ApL[r0]; al_[mf][1] = ApL[r0 + 8 * GAS];
                al_[mf][2] = ApL[r1]; al_[mf][3] = ApL[r1 + 8 * GAS];
            }
#pragma unroll
            for (int nf = 0; nf < 4; nf++) {
                int n = wn * 32 + nf * 8 + lq;
                int b0i = (ks * 8 + lr) * GBS + n;
                int b1i = (ks * 8 + 4 + lr) * GBS + n;
                uint32_t bh[2] = {BpH[b0i], BpH[b1i]};
                uint32_t bl[2] = {BpL[b0i], BpL[b1i]};
#pragma unroll
                for (int mf = 0; mf < 4; mf++) {
                    mma16(acc[mf][nf], ah[mf], bh);
                    mma16(acc[mf][nf], al_[mf], bh);
                    mma16(acc[mf][nf], ah[mf], bl);
                }
            }
        }
    }

#pragma unroll
    for (int mf = 0; mf < 4; mf++) {
        int o = o0 + wm * 64 + mf * 16 + lq;
        float b0 = biasPerBatch ? bias[bb * M + o] : bias[o];
        float b1 = biasPerBatch ? bias[bb * M + o + 8] : bias[o + 8];
#pragma unroll
        for (int nf = 0; nf < 4; nf++) {
            int n = n0 + wn * 32 + nf * 8 + 2 * lr;
            float2 v0 = make_float2(acc[mf][nf][0] + b0, acc[mf][nf][1] + b0);
            float2 v1 = make_float2(acc[mf][nf][2] + b1, acc[mf][nf][3] + b1);
            *(float2*)(out + ((size_t)bb * M + o) * NTOK + n) = v0;
            *(float2*)(out + ((size_t)bb * M + o + 8) * NTOK + n) = v1;
        }
    }
}

// ---------------------------------------------------------------------------
// Attention (fp16). S = Q^T K 3-term; P = fp16(exp(S)) unsplit;
// O^T = P V with V 2-term (2 MMAs). Block = (head-batch, 128-q tile), 8 warps.
// ---------------------------------------------------------------------------
#define QKS 136    // Qp/Kp stride (uint32), rows = c2 (32)
#define VS2 68     // Vp stride (uint32), rows = c (64)
#define PS2 68     // Ps stride (uint32), rows = t (128)
#define PFP 136    // float-view stride for final transpose
#define ATT_SMEM ((4 * 32 * QKS + 2 * 64 * VS2 + 128 * PS2) * 4 + 512)

__global__ void __launch_bounds__(256) k_attn_b() {
    extern __shared__ uint32_t su[];
    uint32_t* QpH = su;                    // [32 c2][QKS t]
    uint32_t* QpL = QpH + 32 * QKS;
    uint32_t* KpH = QpL + 32 * QKS;        // [32 c2][QKS s]
    uint32_t* KpL = KpH + 32 * QKS;
    uint32_t* VpH = KpL + 32 * QKS;        // [64 c][VS2 s2]
    uint32_t* VpL = VpH + 64 * VS2;
    uint32_t* PsH = VpL + 64 * VS2;        // [128 t][PS2 s2]
    float*    Ls  = (float*)(PsH + 128 * PS2);

    int hb = blockIdx.x >> 4, qt = blockIdx.x & 15;
    int b = hb >> 2, h = hb & 3;
    const float* qbase = g_qkv + (size_t)(b * 768 + h * 192) * NTOK;
    const float* kbase = qbase + (size_t)64 * NTOK;
    const float* vbase = qbase + (size_t)128 * NTOK;
    int tid = threadIdx.x, lane = tid & 31, wid = tid >> 5;
    int wt = wid >> 1, ws = wid & 1;
    int lq = lane >> 2, lr = lane & 3;
    int t0 = qt * 128;

    if (tid < 128) Ls[tid] = 0.f;

    // Q tile: pairs along c, scaled by 1/8
#pragma unroll
    for (int r = 0; r < 4; r++) {
        int idx = tid + r * 256;
        int c2 = idx >> 5, t4 = (idx & 31) << 2;
        const float* qp = qbase + (size_t)(2 * c2) * NTOK + t0 + t4;
        float4 q0 = *(const float4*)(qp);
        float4 q1 = *(const float4*)(qp + NTOK);
        q0.x *= 0.125f; q0.y *= 0.125f; q0.z *= 0.125f; q0.w *= 0.125f;
        q1.x *= 0.125f; q1.y *= 0.125f; q1.z *= 0.125f; q1.w *= 0.125f;
        uint32_t hh[4], ll[4];
        pack2(q0.x, q1.x, hh[0], ll[0]);
        pack2(q0.y, q1.y, hh[1], ll[1]);
        pack2(q0.z, q1.z, hh[2], ll[2]);
        pack2(q0.w, q1.w, hh[3], ll[3]);
        *(uint4*)(QpH + c2 * QKS + t4) = make_uint4(hh[0], hh[1], hh[2], hh[3]);
        *(uint4*)(QpL + c2 * QKS + t4) = make_uint4(ll[0], ll[1], ll[2], ll[3]);
    }

    float accO[8][4];
#pragma unroll
    for (int i = 0; i < 8; i++)
#pragma unroll
        for (int r = 0; r < 4; r++) accO[i][r] = 0.f;
    float lsum[4] = {0.f, 0.f, 0.f, 0.f};

    for (int st = 0; st < 16; st++) {
        int s0 = st * 128;
        // K tile: pairs along c
#pragma unroll
        for (int r = 0; r < 4; r++) {
            int idx = tid + r * 256;
            int c2 = idx >> 5, s4 = (idx & 31) << 2;
            const float* kp = kbase + (size_t)(2 * c2) * NTOK + s0 + s4;
            float4 k0v = *(const float4*)(kp);
            float4 k1v = *(const float4*)(kp + NTOK);
            uint32_t hh[4], ll[4];
            pack2(k0v.x, k1v.x, hh[0], ll[0]);
            pack2(k0v.y, k1v.y, hh[1], ll[1]);
            pack2(k0v.z, k1v.z, hh[2], ll[2]);
            pack2(k0v.w, k1v.w, hh[3], ll[3]);
            *(uint4*)(KpH + c2 * QKS + s4) = make_uint4(hh[0], hh[1], hh[2], hh[3]);
            *(uint4*)(KpL + c2 * QKS + s4) = make_uint4(ll[0], ll[1], ll[2], ll[3]);
        }
        // V tile: natural pairs along s
#pragma unroll
        for (int r = 0; r < 8; r++) {
            int idx = tid + r * 256;
            int c = idx >> 5, sg = idx & 31;
            const float* vp = vbase + (size_t)c * NTOK + s0 + sg * 4;
            float4 v = *(const float4*)(vp);
            uint32_t h0, l0, h1, l1;
            pack2(v.x, v.y, h0, l0);
            pack2(v.z, v.w, h1, l1);
            *(uint2*)(VpH + c * VS2 + sg * 2) = make_uint2(h0, h1);
            *(uint2*)(VpL + c * VS2 + sg * 2) = make_uint2(l0, l1);
        }
        __syncthreads();

        // ------- phase 1: S = Q^T K (3-term) -------
        float accS[2][8][4];
#pragma unroll
        for (int i = 0; i < 2; i++)
#pragma unroll
            for (int j = 0; j < 8; j++)
#pragma unroll
                for (int r = 0; r < 4; r++) accS[i][j][r] = 0.f;

#pragma unroll
        for (int ks = 0; ks < 4; ks++) {
            uint32_t ah[2][4], al_[2][4];
#pragma unroll
            for (int mf = 0; mf < 2; mf++) {
                int t = wt * 32 + mf * 16 + lq;
                int r0 = (ks * 8 + lr) * QKS + t;
                int r1 = (ks * 8 + 4 + lr) * QKS + t;
                ah[mf][0] = QpH[r0]; ah[mf][1] = QpH[r0 + 8];
                ah[mf][2] = QpH[r1]; ah[mf][3] = QpH[r1 + 8];
                al_[mf][0] = QpL[r0]; al_[mf][1] = QpL[r0 + 8];
                al_[mf][2] = QpL[r1]; al_[mf][3] = QpL[r1 + 8];
            }
#pragma unroll
            for (int nf = 0; nf < 8; nf++) {
                int s = ws * 64 + nf * 8 + lq;
                int b0i = (ks * 8 + lr) * QKS + s;
                int b1i = (ks * 8 + 4 + lr) * QKS + s;
                uint32_t bh[2] = {KpH[b0i], KpH[b1i]};
                uint32_t bl[2] = {KpL[b0i], KpL[b1i]};
#pragma unroll
                for (int mf = 0; mf < 2; mf++) {
                    mma16(accS[mf][nf], ah[mf], bh);
                    mma16(accS[mf][nf], al_[mf], bh);
                    mma16(accS[mf][nf], ah[mf], bl);
                }
            }
        }

        // exp, row sums, pack P pairs along s (fp16, unsplit)
#pragma unroll
        for (int mf = 0; mf < 2; mf++) {
            int t = wt * 32 + mf * 16 + lq;
#pragma unroll
            for (int nf = 0; nf < 8; nf++) {
                int s2 = ws * 32 + nf * 4 + lr;
                float e0 = __expf(accS[mf][nf][0]);
                float e1 = __expf(accS[mf][nf][1]);
                float e2 = __expf(accS[mf][nf][2]);
                float e3 = __expf(accS[mf][nf][3]);
                lsum[mf * 2 + 0] += e0 + e1;
                lsum[mf * 2 + 1] += e2 + e3;
                PsH[t * PS2 + s2]       = pack_h(e0, e1);
                PsH[(t + 8) * PS2 + s2] = pack_h(e2, e3);
            }
        }
        __syncthreads();

        // ------- phase 2: O^T[t][c] += P[t][s] * V[c][s] (2 MMAs) -------
        int tb = wid * 16 + lq;
#pragma unroll
        for (int ks = 0; ks < 8; ks++) {
            int p0 = tb * PS2 + ks * 8 + lr;
            uint32_t ah[4];
            ah[0] = PsH[p0];     ah[1] = PsH[p0 + 8 * PS2];
            ah[2] = PsH[p0 + 4]; ah[3] = PsH[p0 + 8 * PS2 + 4];
#pragma unroll
            for (int nf = 0; nf < 8; nf++) {
                int c = nf * 8 + lq;
                int b0i = c * VS2 + ks * 8 + lr;
                uint32_t bh[2] = {VpH[b0i], VpH[b0i + 4]};
                uint32_t bl[2] = {VpL[b0i], VpL[b0i + 4]};
                mma16(accO[nf], ah, bh);
                mma16(accO[nf], ah, bl);
            }
        }
        __syncthreads();
    }

    // reduce row sums into Ls
#pragma unroll
    for (int i = 0; i < 4; i++) {
        lsum[i] += __shfl_xor_sync(0xffffffffu, lsum[i], 1);
        lsum[i] += __shfl_xor_sync(0xffffffffu, lsum[i], 2);
    }
    if (lr == 0) {
        atomicAdd(&Ls[wt * 32 + lq],          lsum[0]);
        atomicAdd(&Ls[wt * 32 + lq + 8],      lsum[1]);
        atomicAdd(&Ls[wt * 32 + 16 + lq],     lsum[2]);
        atomicAdd(&Ls[wt * 32 + 16 + lq + 8], lsum[3]);
    }
    __syncthreads();

    // normalize + transpose via float scratch (overwrites Q/K tiles)
    float* Pf = (float*)su;    // [64 c][PFP t]
    float inv0 = 1.f / Ls[wid * 16 + lq];
    float inv1 = 1.f / Ls[wid * 16 + lq + 8];
    int t = wid * 16 + lq;
#pragma unroll
    for (int nf = 0; nf < 8; nf++) {
        int cc = nf * 8 + 2 * lr;
        Pf[cc * PFP + t]           = accO[nf][0] * inv0;
        Pf[(cc + 1) * PFP + t]     = accO[nf][1] * inv0;
        Pf[cc * PFP + t + 8]       = accO[nf][2] * inv1;
        Pf[(cc + 1) * PFP + t + 8] = accO[nf][3] * inv1;
    }
    __syncthreads();

    int rowbase = b * 256 + h * 64;
#pragma unroll
    for (int r = 0; r < 8; r++) {
        int idx = tid + r * 256;
        int c = idx >> 5, t4 = (idx & 31) << 2;
        float4 v = *(const float4*)(Pf + c * PFP + t4);
        *(float4*)(g_attn + (size_t)(rowbase + c) * NTOK + t0 + t4) = v;
    }
}

// ---------------------------------------------------------------------------
// Inverse FFT2
// ---------------------------------------------------------------------------
__global__ void __launch_bounds__(32) k_ifft(float* __restrict__ outp) {
    __shared__ float sr[32][33];
    __shared__ float si[32][33];
    __shared__ float2 tw[32];

    int img  = blockIdx.x;
    int lane = threadIdx.x;

    float sn, cs;
    __sincosf(6.283185307179586f * (float)lane / 32.f, &sn, &cs);
    tw[lane] = make_float2(cs, sn);

    const float* ip = g_proj + (size_t)img * NTOK;
#pragma unroll
    for (int y = 0; y < 32; y++) {
        sr[y][lane] = ip[(y * 32 + lane) * 2 + 0];
        si[y][lane] = ip[(y * 32 + lane) * 2 + 1];
    }
    __syncwarp();

    float cr[32], ci[32];
#pragma unroll
    for (int j = 0; j < 32; j++) { cr[j] = sr[lane][j]; ci[j] = si[lane][j]; }
    __syncwarp();

    for (int k = 0; k < 32; k++) {
        float ar = 0.f, ai = 0.f;
#pragma unroll
        for (int j = 0; j < 32; j++) {
            float2 w = tw[(j * k) & 31];
            ar += cr[j] * w.x - ci[j] * w.y;
            ai += cr[j] * w.y + ci[j] * w.x;
        }
        sr[k][lane] = ar;
        si[k][lane] = ai;
    }
    __syncwarp();

#pragma unroll
    for (int j = 0; j < 32; j++) { cr[j] = sr[lane][j]; ci[j] = si[lane][j]; }

    float* op = outp + (size_t)img * NTOK;
    for (int k = 0; k < 32; k++) {
        float ar = 0.f, ai = 0.f;
#pragma unroll
        for (int j = 0; j < 32; j++) {
            float2 w = tw[(j * k) & 31];
            ar += cr[j] * w.x - ci[j] * w.y;
            ai += cr[j] * w.y + ci[j] * w.x;
        }
        op[(k * 32 + lane) * 2 + 0] = ar * (1.f / 1024.f);
        op[(k * 32 + lane) * 2 + 1] = ai * (1.f / 1024.f);
    }
}

// ---------------------------------------------------------------------------
extern "C" void kernel_launch(void* const* d_in, const int* in_sizes, int n_in,
                              void* d_out, int out_size) {
    const float* x      = (const float*)d_in[0];
    const float* gn_w   = (const float*)d_in[1];
    const float* gn_b   = (const float*)d_in[2];
    const float* qkv_w  = (const float*)d_in[3];
    const float* qkv_b  = (const float*)d_in[4];
    const float* proj_w = (const float*)d_in[5];
    const float* proj_b = (const float*)d_in[6];
    float* out = (float*)d_out;

    float *p_xr, *p_qkv, *p_attn, *p_proj, *p_alpha, *p_bb;
    cudaGetSymbolAddress((void**)&p_xr,    g_xr);
    cudaGetSymbolAddress((void**)&p_qkv,   g_qkv);
    cudaGetSymbolAddress((void**)&p_attn,  g_attn);
    cudaGetSymbolAddress((void**)&p_proj,  g_proj);
    cudaGetSymbolAddress((void**)&p_alpha, g_alpha);
    cudaGetSymbolAddress((void**)&p_bb,    g_bb);

    cudaFuncSetAttribute(k_attn_b, cudaFuncAttributeMaxDynamicSharedMemorySize, ATT_SMEM);
    cudaFuncSetAttribute(k_gemm_b, cudaFuncAttributeMaxDynamicSharedMemorySize, GEMM_SMEM);

    k_zero_stats<<<1, 512>>>();
    k_fft<<<2048, 32>>>(x);
    k_prep_ab<<<8, 256>>>(gn_w, gn_b);
    k_prep_bb<<<768, 256>>>(qkv_w, qkv_b);
    k_gemm_b<<<dim3(16, 6, 8), 256, GEMM_SMEM>>>(qkv_w, p_xr, p_alpha, p_bb, 768, 1, p_qkv);
    k_attn_b<<<512, 256, ATT_SMEM>>>();
    k_gemm_b<<<dim3(16, 2, 8), 256, GEMM_SMEM>>>(proj_w, p_attn, nullptr, proj_b, 256, 0, p_proj);
    k_ifft<<<2048, 32>>>(out);
}

// round 13
// speedup vs baseline: 2.5360x; 1.2154x over previous
#include <cuda_runtime.h>
#include <cuda_fp16.h>
#include <cstdint>
#include <cstddef>

// ---------------------------------------------------------------------------
// FFTAttention: fft2 -> GroupNorm -> QKV gemm -> attention -> proj -> ifft2
// b=8, c=256, h=w=32, n=2048, heads=4, ch=64.
// GEMMs: fp16 m16n8k16 mma 3-term hi/lo (~2^-22).
// Attention: S = Qhi/lo x Khi (2-term), P = fp16(exp(S)), O = P x Vhi (1-term).
// ---------------------------------------------------------------------------

#define NTOK 2048

__device__ float g_xr  [8 * 256 * NTOK];
__device__ float g_qkv [8 * 768 * NTOK];
__device__ float g_attn[8 * 256 * NTOK];
__device__ float g_proj[8 * 256 * NTOK];
__device__ float g_alpha[8 * 256];
__device__ float g_beta [8 * 256];
__device__ float g_bb   [8 * 768];
__device__ float g_stats[512];

// ---------------- fp16 helpers ----------------
__device__ __forceinline__ uint32_t pack_h(float x0, float x1) {
    uint32_t h;
    asm("cvt.rn.f16x2.f32 %0, %1, %2;" : "=r"(h) : "f"(x1), "f"(x0));
    return h;
}
__device__ __forceinline__ void pack2(float x0, float x1, uint32_t& h, uint32_t& l) {
    asm("cvt.rn.f16x2.f32 %0, %1, %2;" : "=r"(h) : "f"(x1), "f"(x0));
    __half2 hh = *reinterpret_cast<const __half2*>(&h);
    float r0 = x0 - __low2float(hh);
    float r1 = x1 - __high2float(hh);
    asm("cvt.rn.f16x2.f32 %0, %1, %2;" : "=r"(l) : "f"(r1), "f"(r0));
}
__device__ __forceinline__ void mma16(float* d, const uint32_t* a, const uint32_t* b) {
    asm volatile(
        "mma.sync.aligned.m16n8k16.row.col.f32.f16.f16.f32 "
        "{%0,%1,%2,%3}, {%4,%5,%6,%7}, {%8,%9}, {%0,%1,%2,%3};\n"
        : "+f"(d[0]), "+f"(d[1]), "+f"(d[2]), "+f"(d[3])
        : "r"(a[0]), "r"(a[1]), "r"(a[2]), "r"(a[3]), "r"(b[0]), "r"(b[1]));
}

__global__ void k_zero_stats() { g_stats[threadIdx.x] = 0.f; }

// ---------------------------------------------------------------------------
// Forward FFT2 + groupnorm stats (one warp per (b,c) image)
// ---------------------------------------------------------------------------
__global__ void __launch_bounds__(32) k_fft(const float* __restrict__ x) {
    __shared__ float sr[32][33];
    __shared__ float si[32][33];
    __shared__ float2 tw[32];

    int img  = blockIdx.x;
    int lane = threadIdx.x;

    float sn, cs;
    __sincosf(-6.283185307179586f * (float)lane / 32.f, &sn, &cs);
    tw[lane] = make_float2(cs, sn);

    const float* xin = x + (size_t)img * 1024;
#pragma unroll
    for (int y = 0; y < 32; y++) sr[y][lane] = xin[y * 32 + lane];
    __syncwarp();

    float vr[32];
#pragma unroll
    for (int j = 0; j < 32; j++) vr[j] = sr[lane][j];
    __syncwarp();

    for (int k = 0; k < 32; k++) {
        float ar = 0.f, ai = 0.f;
#pragma unroll
        for (int j = 0; j < 32; j++) {
            float2 w = tw[(j * k) & 31];
            ar += vr[j] * w.x;
            ai += vr[j] * w.y;
        }
        sr[k][lane] = ar;
        si[k][lane] = ai;
    }
    __syncwarp();

    float cr[32], ci[32];
#pragma unroll
    for (int t = 0; t < 32; t++) { cr[t] = sr[lane][t]; ci[t] = si[lane][t]; }

    float* outp = g_xr + (size_t)img * NTOK;
    float sum = 0.f, ssq = 0.f;
    for (int k = 0; k < 32; k++) {
        float ar = 0.f, ai = 0.f;
#pragma unroll
        for (int j = 0; j < 32; j++) {
            float2 w = tw[(j * k) & 31];
            ar += cr[j] * w.x - ci[j] * w.y;
            ai += cr[j] * w.y + ci[j] * w.x;
        }
        outp[(k * 32 + lane) * 2 + 0] = ar;
        outp[(k * 32 + lane) * 2 + 1] = ai;
        sum += ar + ai;
        ssq += ar * ar + ai * ai;
    }

#pragma unroll
    for (int off = 16; off > 0; off >>= 1) {
        sum += __shfl_xor_sync(0xffffffffu, sum, off);
        ssq += __shfl_xor_sync(0xffffffffu, ssq, off);
    }
    if (lane == 0) {
        int b  = img >> 8;
        int ch = img & 255;
        int grp = b * 32 + (ch >> 3);
        atomicAdd(&g_stats[grp * 2 + 0], sum);
        atomicAdd(&g_stats[grp * 2 + 1], ssq);
    }
}

__global__ void k_prep_ab(const float* __restrict__ gn_w, const float* __restrict__ gn_b) {
    int b = blockIdx.x;
    int c = threadIdx.x;
    int grp = b * 32 + (c >> 3);
    float s0 = g_stats[grp * 2 + 0];
    float s1 = g_stats[grp * 2 + 1];
    float mean = s0 * (1.f / 16384.f);
    float var  = s1 * (1.f / 16384.f) - mean * mean;
    float rs   = rsqrtf(var + 1e-5f);
    float w = gn_w[c];
    g_alpha[b * 256 + c] = rs * w;
    g_beta [b * 256 + c] = gn_b[c] - mean * rs * w;
}

__global__ void __launch_bounds__(256) k_prep_bb(const float* __restrict__ qkv_w,
                                                 const float* __restrict__ qkv_b) {
    int w = (blockIdx.x * 256 + threadIdx.x) >> 5;
    int lane = threadIdx.x & 31;
    int b = w / 768, o = w - b * 768;
    const float* wr = qkv_w + (size_t)o * 256;
    const float* be = g_beta + b * 256;
    float acc = 0.f;
#pragma unroll
    for (int c = lane; c < 256; c += 32) acc += wr[c] * be[c];
#pragma unroll
    for (int off = 16; off > 0; off >>= 1) acc += __shfl_xor_sync(0xffffffffu, acc, off);
    if (lane == 0) g_bb[w] = acc + qkv_b[o];
}

// ---------------------------------------------------------------------------
// fp16-3x GEMM: out[b][o][n] = bias + sum_c A[o][c]*(alpha[b][c])*X[b][c][n]
// block 128x128, K-chunk 32 (16 c-pairs), 8 warps (2x4), warp 64x32.
// ---------------------------------------------------------------------------
#define GAS 20
#define GBS 136
#define GEMM_SMEM ((2 * 128 * GAS + 2 * 16 * GBS) * 4)

__global__ void __launch_bounds__(256, 2) k_gemm_b(
    const float* __restrict__ A, const float* __restrict__ X,
    const float* __restrict__ alpha, const float* __restrict__ bias,
    int M, int biasPerBatch, float* __restrict__ out)
{
    extern __shared__ uint32_t sg[];
    uint32_t* ApH = sg;
    uint32_t* ApL = ApH + 128 * GAS;
    uint32_t* BpH = ApL + 128 * GAS;
    uint32_t* BpL = BpH + 16 * GBS;

    int n0 = blockIdx.x * 128, o0 = blockIdx.y * 128, bb = blockIdx.z;
    int tid = threadIdx.x, lane = tid & 31, wid = tid >> 5;
    int wm = wid >> 2, wn = wid & 3;
    int lq = lane >> 2, lr = lane & 3;
    const float* Xb = X + (size_t)bb * 256 * NTOK;
    bool useAlpha = (alpha != nullptr);

    float acc[4][4][4];
#pragma unroll
    for (int i = 0; i < 4; i++)
#pragma unroll
        for (int j = 0; j < 4; j++)
#pragma unroll
            for (int r = 0; r < 4; r++) acc[i][j][r] = 0.f;

    for (int k0 = 0; k0 < 256; k0 += 32) {
        __syncthreads();
#pragma unroll
        for (int r = 0; r < 2; r++) {
            int idx = tid + r * 256;
            int row = idx >> 2, cq = idx & 3;
            const float* ap = A + (size_t)(o0 + row) * 256 + k0 + cq * 8;
            float4 v0 = *(const float4*)(ap);
            float4 v1 = *(const float4*)(ap + 4);
            uint32_t h[4], l[4];
            pack2(v0.x, v0.y, h[0], l[0]);
            pack2(v0.z, v0.w, h[1], l[1]);
            pack2(v1.x, v1.y, h[2], l[2]);
            pack2(v1.z, v1.w, h[3], l[3]);
            *(uint4*)(ApH + row * GAS + cq * 4) = make_uint4(h[0], h[1], h[2], h[3]);
            *(uint4*)(ApL + row * GAS + cq * 4) = make_uint4(l[0], l[1], l[2], l[3]);
        }
#pragma unroll
        for (int r = 0; r < 2; r++) {
            int idx = tid + r * 256;
            int c2 = idx >> 5, n4 = (idx & 31) << 2;
            const float* xp = Xb + (size_t)(k0 + 2 * c2) * NTOK + n0 + n4;
            float4 x0 = *(const float4*)(xp);
            float4 x1 = *(const float4*)(xp + NTOK);
            if (useAlpha) {
                float a0 = alpha[bb * 256 + k0 + 2 * c2];
                float a1 = alpha[bb * 256 + k0 + 2 * c2 + 1];
                x0.x *= a0; x0.y *= a0; x0.z *= a0; x0.w *= a0;
                x1.x *= a1; x1.y *= a1; x1.z *= a1; x1.w *= a1;
            }
            uint32_t h[4], l[4];
            pack2(x0.x, x1.x, h[0], l[0]);
            pack2(x0.y, x1.y, h[1], l[1]);
            pack2(x0.z, x1.z, h[2], l[2]);
            pack2(x0.w, x1.w, h[3], l[3]);
            *(uint4*)(BpH + c2 * GBS + n4) = make_uint4(h[0], h[1], h[2], h[3]);
            *(uint4*)(BpL + c2 * GBS + n4) = make_uint4(l[0], l[1], l[2], l[3]);
        }
        __syncthreads();

#pragma unroll
        for (int ks = 0; ks < 2; ks++) {
            uint32_t ah[4][4], al_[4][4];
#pragma unroll
            for (int mf = 0; mf < 4; mf++) {
                int m = wm * 64 + mf * 16 + lq;
                int r0 = m * GAS + ks * 8 + lr;
                int r1 = r0 + 4;
                ah[mf][0] = ApH[r0]; ah[mf][1] = ApH[r0 + 8 * GAS];
                ah[mf][2] = ApH[r1]; ah[mf][3] = ApH[r1 + 8 * GAS];
                al_[mf][0] = ApL[r0]; al_[mf][1] = ApL[r0 + 8 * GAS];
                al_[mf][2] = ApL[r1]; al_[mf][3] = ApL[r1 + 8 * GAS];
            }
#pragma unroll
            for (int nf = 0; nf < 4; nf++) {
                int n = wn * 32 + nf * 8 + lq;
                int b0i = (ks * 8 + lr) * GBS + n;
                int b1i = (ks * 8 + 4 + lr) * GBS + n;
                uint32_t bh[2] = {BpH[b0i], BpH[b1i]};
                uint32_t bl[2] = {BpL[b0i], BpL[b1i]};
#pragma unroll
                for (int mf = 0; mf < 4; mf++) {
                    mma16(acc[mf][nf], ah[mf], bh);
                    mma16(acc[mf][nf], al_[mf], bh);
                    mma16(acc[mf][nf], ah[mf], bl);
                }
            }
        }
    }

#pragma unroll
    for (int mf = 0; mf < 4; mf++) {
        int o = o0 + wm * 64 + mf * 16 + lq;
        float b0 = biasPerBatch ? bias[bb * M + o] : bias[o];
        float b1 = biasPerBatch ? bias[bb * M + o + 8] : bias[o + 8];
#pragma unroll
        for (int nf = 0; nf < 4; nf++) {
            int n = n0 + wn * 32 + nf * 8 + 2 * lr;
            float2 v0 = make_float2(acc[mf][nf][0] + b0, acc[mf][nf][1] + b0);
            float2 v1 = make_float2(acc[mf][nf][2] + b1, acc[mf][nf][3] + b1);
            *(float2*)(out + ((size_t)bb * M + o) * NTOK + n) = v0;
            *(float2*)(out + ((size_t)bb * M + o + 8) * NTOK + n) = v1;
        }
    }
}

// ---------------------------------------------------------------------------
// Attention (fp16). S = Qhi/lo x Khi (2 MMAs, s processed in 2 halves);
// P = fp16(exp(S)); O^T = P x Vhi (1 MMA). 8 warps, occ 2.
// ---------------------------------------------------------------------------
#define QKS 136    // Qp/Kp stride (uint32), rows = c2 (32)
#define VS2 68     // Vp stride (uint32), rows = c (64)
#define PS2 68     // Ps stride (uint32), rows = t (128)
#define PFP 136    // float-view stride for final transpose
#define ATT_SMEM ((3 * 32 * QKS + 64 * VS2 + 128 * PS2) * 4 + 512)

__global__ void __launch_bounds__(256, 2) k_attn_b() {
    extern __shared__ uint32_t su[];
    uint32_t* QpH = su;                    // [32 c2][QKS t]
    uint32_t* QpL = QpH + 32 * QKS;
    uint32_t* KpH = QpL + 32 * QKS;        // [32 c2][QKS s]
    uint32_t* VpH = KpH + 32 * QKS;        // [64 c][VS2 s2]
    uint32_t* PsH = VpH + 64 * VS2;        // [128 t][PS2 s2]
    float*    Ls  = (float*)(PsH + 128 * PS2);

    int hb = blockIdx.x >> 4, qt = blockIdx.x & 15;
    int b = hb >> 2, h = hb & 3;
    const float* qbase = g_qkv + (size_t)(b * 768 + h * 192) * NTOK;
    const float* kbase = qbase + (size_t)64 * NTOK;
    const float* vbase = qbase + (size_t)128 * NTOK;
    int tid = threadIdx.x, lane = tid & 31, wid = tid >> 5;
    int wt = wid >> 1, ws = wid & 1;
    int lq = lane >> 2, lr = lane & 3;
    int t0 = qt * 128;

    if (tid < 128) Ls[tid] = 0.f;

    // Q tile: pairs along c, scaled by 1/8, hi+lo planes
#pragma unroll
    for (int r = 0; r < 4; r++) {
        int idx = tid + r * 256;
        int c2 = idx >> 5, t4 = (idx & 31) << 2;
        const float* qp = qbase + (size_t)(2 * c2) * NTOK + t0 + t4;
        float4 q0 = *(const float4*)(qp);
        float4 q1 = *(const float4*)(qp + NTOK);
        q0.x *= 0.125f; q0.y *= 0.125f; q0.z *= 0.125f; q0.w *= 0.125f;
        q1.x *= 0.125f; q1.y *= 0.125f; q1.z *= 0.125f; q1.w *= 0.125f;
        uint32_t hh[4], ll[4];
        pack2(q0.x, q1.x, hh[0], ll[0]);
        pack2(q0.y, q1.y, hh[1], ll[1]);
        pack2(q0.z, q1.z, hh[2], ll[2]);
        pack2(q0.w, q1.w, hh[3], ll[3]);
        *(uint4*)(QpH + c2 * QKS + t4) = make_uint4(hh[0], hh[1], hh[2], hh[3]);
        *(uint4*)(QpL + c2 * QKS + t4) = make_uint4(ll[0], ll[1], ll[2], ll[3]);
    }

    float accO[8][4];
#pragma unroll
    for (int i = 0; i < 8; i++)
#pragma unroll
        for (int r = 0; r < 4; r++) accO[i][r] = 0.f;
    float lsum[4] = {0.f, 0.f, 0.f, 0.f};

    for (int st = 0; st < 16; st++) {
        int s0 = st * 128;
        // K tile: pairs along c, hi only
#pragma unroll
        for (int r = 0; r < 4; r++) {
            int idx = tid + r * 256;
            int c2 = idx >> 5, s4 = (idx & 31) << 2;
            const float* kp = kbase + (size_t)(2 * c2) * NTOK + s0 + s4;
            float4 k0v = *(const float4*)(kp);
            float4 k1v = *(const float4*)(kp + NTOK);
            uint32_t hh[4];
            hh[0] = pack_h(k0v.x, k1v.x);
            hh[1] = pack_h(k0v.y, k1v.y);
            hh[2] = pack_h(k0v.z, k1v.z);
            hh[3] = pack_h(k0v.w, k1v.w);
            *(uint4*)(KpH + c2 * QKS + s4) = make_uint4(hh[0], hh[1], hh[2], hh[3]);
        }
        // V tile: natural pairs along s, hi only
#pragma unroll
        for (int r = 0; r < 8; r++) {
            int idx = tid + r * 256;
            int c = idx >> 5, sg = idx & 31;
            const float* vp = vbase + (size_t)c * NTOK + s0 + sg * 4;
            float4 v = *(const float4*)(vp);
            uint32_t h0 = pack_h(v.x, v.y);
            uint32_t h1 = pack_h(v.z, v.w);
            *(uint2*)(VpH + c * VS2 + sg * 2) = make_uint2(h0, h1);
        }
        __syncthreads();

        // ------- phase 1: S = Q^T K, two 32-column halves per warp -------
#pragma unroll
        for (int half = 0; half < 2; half++) {
            float accS[2][4][4];
#pragma unroll
            for (int i = 0; i < 2; i++)
#pragma unroll
                for (int j = 0; j < 4; j++)
#pragma unroll
                    for (int r = 0; r < 4; r++) accS[i][j][r] = 0.f;

#pragma unroll
            for (int ks = 0; ks < 4; ks++) {
                uint32_t ah[2][4], al_[2][4];
#pragma unroll
                for (int mf = 0; mf < 2; mf++) {
                    int t = wt * 32 + mf * 16 + lq;
                    int r0 = (ks * 8 + lr) * QKS + t;
                    int r1 = (ks * 8 + 4 + lr) * QKS + t;
                    ah[mf][0] = QpH[r0]; ah[mf][1] = QpH[r0 + 8];
                    ah[mf][2] = QpH[r1]; ah[mf][3] = QpH[r1 + 8];
                    al_[mf][0] = QpL[r0]; al_[mf][1] = QpL[r0 + 8];
                    al_[mf][2] = QpL[r1]; al_[mf][3] = QpL[r1 + 8];
                }
#pragma unroll
                for (int nf = 0; nf < 4; nf++) {
                    int s = ws * 64 + half * 32 + nf * 8 + lq;
                    int b0i = (ks * 8 + lr) * QKS + s;
                    int b1i = (ks * 8 + 4 + lr) * QKS + s;
                    uint32_t bh[2] = {KpH[b0i], KpH[b1i]};
#pragma unroll
                    for (int mf = 0; mf < 2; mf++) {
                        mma16(accS[mf][nf], ah[mf], bh);
                        mma16(accS[mf][nf], al_[mf], bh);
                    }
                }
            }

            // exp, row sums, pack P pairs along s (fp16)
#pragma unroll
            for (int mf = 0; mf < 2; mf++) {
                int t = wt * 32 + mf * 16 + lq;
#pragma unroll
                for (int nf = 0; nf < 4; nf++) {
                    int s2 = ws * 32 + half * 16 + nf * 4 + lr;
                    float e0 = __expf(accS[mf][nf][0]);
                    float e1 = __expf(accS[mf][nf][1]);
                    float e2 = __expf(accS[mf][nf][2]);
                    float e3 = __expf(accS[mf][nf][3]);
                    lsum[mf * 2 + 0] += e0 + e1;
                    lsum[mf * 2 + 1] += e2 + e3;
                    PsH[t * PS2 + s2]       = pack_h(e0, e1);
                    PsH[(t + 8) * PS2 + s2] = pack_h(e2, e3);
                }
            }
        }
        __syncthreads();

        // ------- phase 2: O^T[t][c] += P[t][s] * V[c][s] (1 MMA) -------
        int tb = wid * 16 + lq;
#pragma unroll
        for (int ks = 0; ks < 8; ks++) {
            int p0 = tb * PS2 + ks * 8 + lr;
            uint32_t ah[4];
            ah[0] = PsH[p0];     ah[1] = PsH[p0 + 8 * PS2];
            ah[2] = PsH[p0 + 4]; ah[3] = PsH[p0 + 8 * PS2 + 4];
#pragma unroll
            for (int nf = 0; nf < 8; nf++) {
                int c = nf * 8 + lq;
                int b0i = c * VS2 + ks * 8 + lr;
                uint32_t bh[2] = {VpH[b0i], VpH[b0i + 4]};
                mma16(accO[nf], ah, bh);
            }
        }
        __syncthreads();
    }

    // reduce row sums into Ls
#pragma unroll
    for (int i = 0; i < 4; i++) {
        lsum[i] += __shfl_xor_sync(0xffffffffu, lsum[i], 1);
        lsum[i] += __shfl_xor_sync(0xffffffffu, lsum[i], 2);
    }
    if (lr == 0) {
        atomicAdd(&Ls[wt * 32 + lq],          lsum[0]);
        atomicAdd(&Ls[wt * 32 + lq + 8],      lsum[1]);
        atomicAdd(&Ls[wt * 32 + 16 + lq],     lsum[2]);
        atomicAdd(&Ls[wt * 32 + 16 + lq + 8], lsum[3]);
    }
    __syncthreads();

    // normalize + transpose via float scratch (overwrites Q/K tiles)
    float* Pf = (float*)su;    // [64 c][PFP t]
    float inv0 = 1.f / Ls[wid * 16 + lq];
    float inv1 = 1.f / Ls[wid * 16 + lq + 8];
    int t = wid * 16 + lq;
#pragma unroll
    for (int nf = 0; nf < 8; nf++) {
        int cc = nf * 8 + 2 * lr;
        Pf[cc * PFP + t]           = accO[nf][0] * inv0;
        Pf[(cc + 1) * PFP + t]     = accO[nf][1] * inv0;
        Pf[cc * PFP + t + 8]       = accO[nf][2] * inv1;
        Pf[(cc + 1) * PFP + t + 8] = accO[nf][3] * inv1;
    }
    __syncthreads();

    int rowbase = b * 256 + h * 64;
#pragma unroll
    for (int r = 0; r < 8; r++) {
        int idx = tid + r * 256;
        int c = idx >> 5, t4 = (idx & 31) << 2;
        float4 v = *(const float4*)(Pf + c * PFP + t4);
        *(float4*)(g_attn + (size_t)(rowbase + c) * NTOK + t0 + t4) = v;
    }
}

// ---------------------------------------------------------------------------
// Inverse FFT2
// ---------------------------------------------------------------------------
__global__ void __launch_bounds__(32) k_ifft(float* __restrict__ outp) {
    __shared__ float sr[32][33];
    __shared__ float si[32][33];
    __shared__ float2 tw[32];

    int img  = blockIdx.x;
    int lane = threadIdx.x;

    float sn, cs;
    __sincosf(6.283185307179586f * (float)lane / 32.f, &sn, &cs);
    tw[lane] = make_float2(cs, sn);

    const float* ip = g_proj + (size_t)img * NTOK;
#pragma unroll
    for (int y = 0; y < 32; y++) {
        sr[y][lane] = ip[(y * 32 + lane) * 2 + 0];
        si[y][lane] = ip[(y * 32 + lane) * 2 + 1];
    }
    __syncwarp();

    float cr[32], ci[32];
#pragma unroll
    for (int j = 0; j < 32; j++) { cr[j] = sr[lane][j]; ci[j] = si[lane][j]; }
    __syncwarp();

    for (int k = 0; k < 32; k++) {
        float ar = 0.f, ai = 0.f;
#pragma unroll
        for (int j = 0; j < 32; j++) {
            float2 w = tw[(j * k) & 31];
            ar += cr[j] * w.x - ci[j] * w.y;
            ai += cr[j] * w.y + ci[j] * w.x;
        }
        sr[k][lane] = ar;
        si[k][lane] = ai;
    }
    __syncwarp();

#pragma unroll
    for (int j = 0; j < 32; j++) { cr[j] = sr[lane][j]; ci[j] = si[lane][j]; }

    float* op = outp + (size_t)img * NTOK;
    for (int k = 0; k < 32; k++) {
        float ar = 0.f, ai = 0.f;
#pragma unroll
        for (int j = 0; j < 32; j++) {
            float2 w = tw[(j * k) & 31];
            ar += cr[j] * w.x - ci[j] * w.y;
            ai += cr[j] * w.y + ci[j] * w.x;
        }
        op[(k * 32 + lane) * 2 + 0] = ar * (1.f / 1024.f);
        op[(k * 32 + lane) * 2 + 1] = ai * (1.f / 1024.f);
    }
}

// ---------------------------------------------------------------------------
extern "C" void kernel_launch(void* const* d_in, const int* in_sizes, int n_in,
                              void* d_out, int out_size) {
    const float* x      = (const float*)d_in[0];
    const float* gn_w   = (const float*)d_in[1];
    const float* gn_b   = (const float*)d_in[2];
    const float* qkv_w  = (const float*)d_in[3];
    const float* qkv_b  = (const float*)d_in[4];
    const float* proj_w = (const float*)d_in[5];
    const float* proj_b = (const float*)d_in[6];
    float* out = (float*)d_out;

    float *p_xr, *p_qkv, *p_attn, *p_proj, *p_alpha, *p_bb;
    cudaGetSymbolAddress((void**)&p_xr,    g_xr);
    cudaGetSymbolAddress((void**)&p_qkv,   g_qkv);
    cudaGetSymbolAddress((void**)&p_attn,  g_attn);
    cudaGetSymbolAddress((void**)&p_proj,  g_proj);
    cudaGetSymbolAddress((void**)&p_alpha, g_alpha);
    cudaGetSymbolAddress((void**)&p_bb,    g_bb);

    cudaFuncSetAttribute(k_attn_b, cudaFuncAttributeMaxDynamicSharedMemorySize, ATT_SMEM);
    cudaFuncSetAttribute(k_gemm_b, cudaFuncAttributeMaxDynamicSharedMemorySize, GEMM_SMEM);

    k_zero_stats<<<1, 512>>>();
    k_fft<<<2048, 32>>>(x);
    k_prep_ab<<<8, 256>>>(gn_w, gn_b);
    k_prep_bb<<<768, 256>>>(qkv_w, qkv_b);
    k_gemm_b<<<dim3(16, 6, 8), 256, GEMM_SMEM>>>(qkv_w, p_xr, p_alpha, p_bb, 768, 1, p_qkv);
    k_attn_b<<<512, 256, ATT_SMEM>>>();
    k_gemm_b<<<dim3(16, 2, 8), 256, GEMM_SMEM>>>(proj_w, p_attn, nullptr, proj_b, 256, 0, p_proj);
    k_ifft<<<2048, 32>>>(out);
}

// round 14
// speedup vs baseline: 2.9162x; 1.1499x over previous
#include <cuda_runtime.h>
#include <cuda_fp16.h>
#include <cstdint>
#include <cstddef>

// ---------------------------------------------------------------------------
// FFTAttention: fft2 -> GroupNorm -> QKV gemm -> attention -> proj -> ifft2
// b=8, c=256, h=w=32, n=2048, heads=4, ch=64.
// GEMMs: fp16 m16n8k16, 2-term (A hi/lo x X_hi).
// Attention: S = Qhi x Khi (1 MMA), P = fp16(exp(S)), O = P x Vhi (1 MMA).
// ---------------------------------------------------------------------------

#define NTOK 2048

__device__ float g_xr  [8 * 256 * NTOK];
__device__ float g_qkv [8 * 768 * NTOK];
__device__ float g_attn[8 * 256 * NTOK];
__device__ float g_proj[8 * 256 * NTOK];
__device__ float g_alpha[8 * 256];
__device__ float g_beta [8 * 256];
__device__ float g_bb   [8 * 768];
__device__ float g_stats[512];

// ---------------- fp16 helpers ----------------
__device__ __forceinline__ uint32_t pack_h(float x0, float x1) {
    uint32_t h;
    asm("cvt.rn.f16x2.f32 %0, %1, %2;" : "=r"(h) : "f"(x1), "f"(x0));
    return h;
}
__device__ __forceinline__ void pack2(float x0, float x1, uint32_t& h, uint32_t& l) {
    asm("cvt.rn.f16x2.f32 %0, %1, %2;" : "=r"(h) : "f"(x1), "f"(x0));
    __half2 hh = *reinterpret_cast<const __half2*>(&h);
    float r0 = x0 - __low2float(hh);
    float r1 = x1 - __high2float(hh);
    asm("cvt.rn.f16x2.f32 %0, %1, %2;" : "=r"(l) : "f"(r1), "f"(r0));
}
__device__ __forceinline__ void mma16(float* d, const uint32_t* a, const uint32_t* b) {
    asm volatile(
        "mma.sync.aligned.m16n8k16.row.col.f32.f16.f16.f32 "
        "{%0,%1,%2,%3}, {%4,%5,%6,%7}, {%8,%9}, {%0,%1,%2,%3};\n"
        : "+f"(d[0]), "+f"(d[1]), "+f"(d[2]), "+f"(d[3])
        : "r"(a[0]), "r"(a[1]), "r"(a[2]), "r"(a[3]), "r"(b[0]), "r"(b[1]));
}

__global__ void k_zero_stats() { g_stats[threadIdx.x] = 0.f; }

// ---------------------------------------------------------------------------
// Forward FFT2 + groupnorm stats (one warp per (b,c) image)
// ---------------------------------------------------------------------------
__global__ void __launch_bounds__(32) k_fft(const float* __restrict__ x) {
    __shared__ float sr[32][33];
    __shared__ float si[32][33];
    __shared__ float2 tw[32];

    int img  = blockIdx.x;
    int lane = threadIdx.x;

    float sn, cs;
    __sincosf(-6.283185307179586f * (float)lane / 32.f, &sn, &cs);
    tw[lane] = make_float2(cs, sn);

    const float* xin = x + (size_t)img * 1024;
#pragma unroll
    for (int y = 0; y < 32; y++) sr[y][lane] = xin[y * 32 + lane];
    __syncwarp();

    float vr[32];
#pragma unroll
    for (int j = 0; j < 32; j++) vr[j] = sr[lane][j];
    __syncwarp();

    for (int k = 0; k < 32; k++) {
        float ar = 0.f, ai = 0.f;
#pragma unroll
        for (int j = 0; j < 32; j++) {
            float2 w = tw[(j * k) & 31];
            ar += vr[j] * w.x;
            ai += vr[j] * w.y;
        }
        sr[k][lane] = ar;
        si[k][lane] = ai;
    }
    __syncwarp();

    float cr[32], ci[32];
#pragma unroll
    for (int t = 0; t < 32; t++) { cr[t] = sr[lane][t]; ci[t] = si[lane][t]; }

    float* outp = g_xr + (size_t)img * NTOK;
    float sum = 0.f, ssq = 0.f;
    for (int k = 0; k < 32; k++) {
        float ar = 0.f, ai = 0.f;
#pragma unroll
        for (int j = 0; j < 32; j++) {
            float2 w = tw[(j * k) & 31];
            ar += cr[j] * w.x - ci[j] * w.y;
            ai += cr[j] * w.y + ci[j] * w.x;
        }
        outp[(k * 32 + lane) * 2 + 0] = ar;
        outp[(k * 32 + lane) * 2 + 1] = ai;
        sum += ar + ai;
        ssq += ar * ar + ai * ai;
    }

#pragma unroll
    for (int off = 16; off > 0; off >>= 1) {
        sum += __shfl_xor_sync(0xffffffffu, sum, off);
        ssq += __shfl_xor_sync(0xffffffffu, ssq, off);
    }
    if (lane == 0) {
        int b  = img >> 8;
        int ch = img & 255;
        int grp = b * 32 + (ch >> 3);
        atomicAdd(&g_stats[grp * 2 + 0], sum);
        atomicAdd(&g_stats[grp * 2 + 1], ssq);
    }
}

__global__ void k_prep_ab(const float* __restrict__ gn_w, const float* __restrict__ gn_b) {
    int b = blockIdx.x;
    int c = threadIdx.x;
    int grp = b * 32 + (c >> 3);
    float s0 = g_stats[grp * 2 + 0];
    float s1 = g_stats[grp * 2 + 1];
    float mean = s0 * (1.f / 16384.f);
    float var  = s1 * (1.f / 16384.f) - mean * mean;
    float rs   = rsqrtf(var + 1e-5f);
    float w = gn_w[c];
    g_alpha[b * 256 + c] = rs * w;
    g_beta [b * 256 + c] = gn_b[c] - mean * rs * w;
}

__global__ void __launch_bounds__(256) k_prep_bb(const float* __restrict__ qkv_w,
                                                 const float* __restrict__ qkv_b) {
    int w = (blockIdx.x * 256 + threadIdx.x) >> 5;
    int lane = threadIdx.x & 31;
    int b = w / 768, o = w - b * 768;
    const float* wr = qkv_w + (size_t)o * 256;
    const float* be = g_beta + b * 256;
    float acc = 0.f;
#pragma unroll
    for (int c = lane; c < 256; c += 32) acc += wr[c] * be[c];
#pragma unroll
    for (int off = 16; off > 0; off >>= 1) acc += __shfl_xor_sync(0xffffffffu, acc, off);
    if (lane == 0) g_bb[w] = acc + qkv_b[o];
}

// ---------------------------------------------------------------------------
// fp16-2x GEMM: out[b][o][n] = bias + sum_c A[o][c]*(alpha[b][c])*X[b][c][n]
// A in hi+lo planes, X hi only. block 128x128, K-chunk 32, 8 warps.
// ---------------------------------------------------------------------------
#define GAS 20
#define GBS 136
#define GEMM_SMEM ((2 * 128 * GAS + 16 * GBS) * 4)

__global__ void __launch_bounds__(256, 2) k_gemm_b(
    const float* __restrict__ A, const float* __restrict__ X,
    const float* __restrict__ alpha, const float* __restrict__ bias,
    int M, int biasPerBatch, float* __restrict__ out)
{
    extern __shared__ uint32_t sg[];
    uint32_t* ApH = sg;
    uint32_t* ApL = ApH + 128 * GAS;
    uint32_t* BpH = ApL + 128 * GAS;

    int n0 = blockIdx.x * 128, o0 = blockIdx.y * 128, bb = blockIdx.z;
    int tid = threadIdx.x, lane = tid & 31, wid = tid >> 5;
    int wm = wid >> 2, wn = wid & 3;
    int lq = lane >> 2, lr = lane & 3;
    const float* Xb = X + (size_t)bb * 256 * NTOK;
    bool useAlpha = (alpha != nullptr);

    float acc[4][4][4];
#pragma unroll
    for (int i = 0; i < 4; i++)
#pragma unroll
        for (int j = 0; j < 4; j++)
#pragma unroll
            for (int r = 0; r < 4; r++) acc[i][j][r] = 0.f;

    for (int k0 = 0; k0 < 256; k0 += 32) {
        __syncthreads();
#pragma unroll
        for (int r = 0; r < 2; r++) {
            int idx = tid + r * 256;
            int row = idx >> 2, cq = idx & 3;
            const float* ap = A + (size_t)(o0 + row) * 256 + k0 + cq * 8;
            float4 v0 = *(const float4*)(ap);
            float4 v1 = *(const float4*)(ap + 4);
            uint32_t h[4], l[4];
            pack2(v0.x, v0.y, h[0], l[0]);
            pack2(v0.z, v0.w, h[1], l[1]);
            pack2(v1.x, v1.y, h[2], l[2]);
            pack2(v1.z, v1.w, h[3], l[3]);
            *(uint4*)(ApH + row * GAS + cq * 4) = make_uint4(h[0], h[1], h[2], h[3]);
            *(uint4*)(ApL + row * GAS + cq * 4) = make_uint4(l[0], l[1], l[2], l[3]);
        }
#pragma unroll
        for (int r = 0; r < 2; r++) {
            int idx = tid + r * 256;
            int c2 = idx >> 5, n4 = (idx & 31) << 2;
            const float* xp = Xb + (size_t)(k0 + 2 * c2) * NTOK + n0 + n4;
            float4 x0 = *(const float4*)(xp);
            float4 x1 = *(const float4*)(xp + NTOK);
            if (useAlpha) {
                float a0 = alpha[bb * 256 + k0 + 2 * c2];
                float a1 = alpha[bb * 256 + k0 + 2 * c2 + 1];
                x0.x *= a0; x0.y *= a0; x0.z *= a0; x0.w *= a0;
                x1.x *= a1; x1.y *= a1; x1.z *= a1; x1.w *= a1;
            }
            uint32_t h[4];
            h[0] = pack_h(x0.x, x1.x);
            h[1] = pack_h(x0.y, x1.y);
            h[2] = pack_h(x0.z, x1.z);
            h[3] = pack_h(x0.w, x1.w);
            *(uint4*)(BpH + c2 * GBS + n4) = make_uint4(h[0], h[1], h[2], h[3]);
        }
        __syncthreads();

#pragma unroll
        for (int ks = 0; ks < 2; ks++) {
            uint32_t ah[4][4], al_[4][4];
#pragma unroll
            for (int mf = 0; mf < 4; mf++) {
                int m = wm * 64 + mf * 16 + lq;
                int r0 = m * GAS + ks * 8 + lr;
                int r1 = r0 + 4;
                ah[mf][0] = ApH[r0]; ah[mf][1] = ApH[r0 + 8 * GAS];
                ah[mf][2] = ApH[r1]; ah[mf][3] = ApH[r1 + 8 * GAS];
                al_[mf][0] = ApL[r0]; al_[mf][1] = ApL[r0 + 8 * GAS];
                al_[mf][2] = ApL[r1]; al_[mf][3] = ApL[r1 + 8 * GAS];
            }
#pragma unroll
            for (int nf = 0; nf < 4; nf++) {
                int n = wn * 32 + nf * 8 + lq;
                int b0i = (ks * 8 + lr) * GBS + n;
                int b1i = (ks * 8 + 4 + lr) * GBS + n;
                uint32_t bh[2] = {BpH[b0i], BpH[b1i]};
#pragma unroll
                for (int mf = 0; mf < 4; mf++) {
                    mma16(acc[mf][nf], ah[mf], bh);
                    mma16(acc[mf][nf], al_[mf], bh);
                }
            }
        }
    }

#pragma unroll
    for (int mf = 0; mf < 4; mf++) {
        int o = o0 + wm * 64 + mf * 16 + lq;
        float b0 = biasPerBatch ? bias[bb * M + o] : bias[o];
        float b1 = biasPerBatch ? bias[bb * M + o + 8] : bias[o + 8];
#pragma unroll
        for (int nf = 0; nf < 4; nf++) {
            int n = n0 + wn * 32 + nf * 8 + 2 * lr;
            float2 v0 = make_float2(acc[mf][nf][0] + b0, acc[mf][nf][1] + b0);
            float2 v1 = make_float2(acc[mf][nf][2] + b1, acc[mf][nf][3] + b1);
            *(float2*)(out + ((size_t)bb * M + o) * NTOK + n) = v0;
            *(float2*)(out + ((size_t)bb * M + o + 8) * NTOK + n) = v1;
        }
    }
}

// ---------------------------------------------------------------------------
// Attention (fp16). S = Qhi x Khi (1 MMA); P = fp16(exp(S)); O^T = P x Vhi.
// 8 warps, occ 2.
// ---------------------------------------------------------------------------
#define QKS 136    // Qp/Kp stride (uint32), rows = c2 (32)
#define VS2 68     // Vp stride (uint32), rows = c (64)
#define PS2 68     // Ps stride (uint32), rows = t (128)
#define PFP 136    // float-view stride for final transpose
#define ATT_SMEM ((2 * 32 * QKS + 64 * VS2 + 128 * PS2) * 4 + 512)

__global__ void __launch_bounds__(256, 2) k_attn_b() {
    extern __shared__ uint32_t su[];
    uint32_t* QpH = su;                    // [32 c2][QKS t]
    uint32_t* KpH = QpH + 32 * QKS;        // [32 c2][QKS s]
    uint32_t* VpH = KpH + 32 * QKS;        // [64 c][VS2 s2]
    uint32_t* PsH = VpH + 64 * VS2;        // [128 t][PS2 s2]
    float*    Ls  = (float*)(PsH + 128 * PS2);

    int hb = blockIdx.x >> 4, qt = blockIdx.x & 15;
    int b = hb >> 2, h = hb & 3;
    const float* qbase = g_qkv + (size_t)(b * 768 + h * 192) * NTOK;
    const float* kbase = qbase + (size_t)64 * NTOK;
    const float* vbase = qbase + (size_t)128 * NTOK;
    int tid = threadIdx.x, lane = tid & 31, wid = tid >> 5;
    int wt = wid >> 1, ws = wid & 1;
    int lq = lane >> 2, lr = lane & 3;
    int t0 = qt * 128;

    if (tid < 128) Ls[tid] = 0.f;

    // Q tile: pairs along c, scaled by 1/8, hi only
#pragma unroll
    for (int r = 0; r < 4; r++) {
        int idx = tid + r * 256;
        int c2 = idx >> 5, t4 = (idx & 31) << 2;
        const float* qp = qbase + (size_t)(2 * c2) * NTOK + t0 + t4;
        float4 q0 = *(const float4*)(qp);
        float4 q1 = *(const float4*)(qp + NTOK);
        q0.x *= 0.125f; q0.y *= 0.125f; q0.z *= 0.125f; q0.w *= 0.125f;
        q1.x *= 0.125f; q1.y *= 0.125f; q1.z *= 0.125f; q1.w *= 0.125f;
        uint32_t hh[4];
        hh[0] = pack_h(q0.x, q1.x);
        hh[1] = pack_h(q0.y, q1.y);
        hh[2] = pack_h(q0.z, q1.z);
        hh[3] = pack_h(q0.w, q1.w);
        *(uint4*)(QpH + c2 * QKS + t4) = make_uint4(hh[0], hh[1], hh[2], hh[3]);
    }

    float accO[8][4];
#pragma unroll
    for (int i = 0; i < 8; i++)
#pragma unroll
        for (int r = 0; r < 4; r++) accO[i][r] = 0.f;
    float lsum[4] = {0.f, 0.f, 0.f, 0.f};

    for (int st = 0; st < 16; st++) {
        int s0 = st * 128;
        // K tile: pairs along c, hi only
#pragma unroll
        for (int r = 0; r < 4; r++) {
            int idx = tid + r * 256;
            int c2 = idx >> 5, s4 = (idx & 31) << 2;
            const float* kp = kbase + (size_t)(2 * c2) * NTOK + s0 + s4;
            float4 k0v = *(const float4*)(kp);
            float4 k1v = *(const float4*)(kp + NTOK);
            uint32_t hh[4];
            hh[0] = pack_h(k0v.x, k1v.x);
            hh[1] = pack_h(k0v.y, k1v.y);
            hh[2] = pack_h(k0v.z, k1v.z);
            hh[3] = pack_h(k0v.w, k1v.w);
            *(uint4*)(KpH + c2 * QKS + s4) = make_uint4(hh[0], hh[1], hh[2], hh[3]);
        }
        // V tile: natural pairs along s, hi only
#pragma unroll
        for (int r = 0; r < 8; r++) {
            int idx = tid + r * 256;
            int c = idx >> 5, sg = idx & 31;
            const float* vp = vbase + (size_t)c * NTOK + s0 + sg * 4;
            float4 v = *(const float4*)(vp);
            uint32_t h0 = pack_h(v.x, v.y);
            uint32_t h1 = pack_h(v.z, v.w);
            *(uint2*)(VpH + c * VS2 + sg * 2) = make_uint2(h0, h1);
        }
        __syncthreads();

        // ------- phase 1: S = Q^T K, two 32-column halves per warp -------
#pragma unroll
        for (int half = 0; half < 2; half++) {
            float accS[2][4][4];
#pragma unroll
            for (int i = 0; i < 2; i++)
#pragma unroll
                for (int j = 0; j < 4; j++)
#pragma unroll
                    for (int r = 0; r < 4; r++) accS[i][j][r] = 0.f;

#pragma unroll
            for (int ks = 0; ks < 4; ks++) {
                uint32_t ah[2][4];
#pragma unroll
                for (int mf = 0; mf < 2; mf++) {
                    int t = wt * 32 + mf * 16 + lq;
                    int r0 = (ks * 8 + lr) * QKS + t;
                    int r1 = (ks * 8 + 4 + lr) * QKS + t;
                    ah[mf][0] = QpH[r0]; ah[mf][1] = QpH[r0 + 8];
                    ah[mf][2] = QpH[r1]; ah[mf][3] = QpH[r1 + 8];
                }
#pragma unroll
                for (int nf = 0; nf < 4; nf++) {
                    int s = ws * 64 + half * 32 + nf * 8 + lq;
                    int b0i = (ks * 8 + lr) * QKS + s;
                    int b1i = (ks * 8 + 4 + lr) * QKS + s;
                    uint32_t bh[2] = {KpH[b0i], KpH[b1i]};
#pragma unroll
                    for (int mf = 0; mf < 2; mf++)
                        mma16(accS[mf][nf], ah[mf], bh);
                }
            }

            // exp, row sums, pack P pairs along s (fp16)
#pragma unroll
            for (int mf = 0; mf < 2; mf++) {
                int t = wt * 32 + mf * 16 + lq;
#pragma unroll
                for (int nf = 0; nf < 4; nf++) {
                    int s2 = ws * 32 + half * 16 + nf * 4 + lr;
                    float e0 = __expf(accS[mf][nf][0]);
                    float e1 = __expf(accS[mf][nf][1]);
                    float e2 = __expf(accS[mf][nf][2]);
                    float e3 = __expf(accS[mf][nf][3]);
                    lsum[mf * 2 + 0] += e0 + e1;
                    lsum[mf * 2 + 1] += e2 + e3;
                    PsH[t * PS2 + s2]       = pack_h(e0, e1);
                    PsH[(t + 8) * PS2 + s2] = pack_h(e2, e3);
                }
            }
        }
        __syncthreads();

        // ------- phase 2: O^T[t][c] += P[t][s] * V[c][s] (1 MMA) -------
        int tb = wid * 16 + lq;
#pragma unroll
        for (int ks = 0; ks < 8; ks++) {
            int p0 = tb * PS2 + ks * 8 + lr;
            uint32_t ah[4];
            ah[0] = PsH[p0];     ah[1] = PsH[p0 + 8 * PS2];
            ah[2] = PsH[p0 + 4]; ah[3] = PsH[p0 + 8 * PS2 + 4];
#pragma unroll
            for (int nf = 0; nf < 8; nf++) {
                int c = nf * 8 + lq;
                int b0i = c * VS2 + ks * 8 + lr;
                uint32_t bh[2] = {VpH[b0i], VpH[b0i + 4]};
                mma16(accO[nf], ah, bh);
            }
        }
        __syncthreads();
    }

    // reduce row sums into Ls
#pragma unroll
    for (int i = 0; i < 4; i++) {
        lsum[i] += __shfl_xor_sync(0xffffffffu, lsum[i], 1);
        lsum[i] += __shfl_xor_sync(0xffffffffu, lsum[i], 2);
    }
    if (lr == 0) {
        atomicAdd(&Ls[wt * 32 + lq],          lsum[0]);
        atomicAdd(&Ls[wt * 32 + lq + 8],      lsum[1]);
        atomicAdd(&Ls[wt * 32 + 16 + lq],     lsum[2]);
        atomicAdd(&Ls[wt * 32 + 16 + lq + 8], lsum[3]);
    }
    __syncthreads();

    // normalize + transpose via float scratch (overwrites Q/K tiles)
    float* Pf = (float*)su;    // [64 c][PFP t]
    float inv0 = 1.f / Ls[wid * 16 + lq];
    float inv1 = 1.f / Ls[wid * 16 + lq + 8];
    int t = wid * 16 + lq;
#pragma unroll
    for (int nf = 0; nf < 8; nf++) {
        int cc = nf * 8 + 2 * lr;
        Pf[cc * PFP + t]           = accO[nf][0] * inv0;
        Pf[(cc + 1) * PFP + t]     = accO[nf][1] * inv0;
        Pf[cc * PFP + t + 8]       = accO[nf][2] * inv1;
        Pf[(cc + 1) * PFP + t + 8] = accO[nf][3] * inv1;
    }
    __syncthreads();

    int rowbase = b * 256 + h * 64;
#pragma unroll
    for (int r = 0; r < 8; r++) {
        int idx = tid + r * 256;
        int c = idx >> 5, t4 = (idx & 31) << 2;
        float4 v = *(const float4*)(Pf + c * PFP + t4);
        *(float4*)(g_attn + (size_t)(rowbase + c) * NTOK + t0 + t4) = v;
    }
}

// ---------------------------------------------------------------------------
// Inverse FFT2
// ---------------------------------------------------------------------------
__global__ void __launch_bounds__(32) k_ifft(float* __restrict__ outp) {
    __shared__ float sr[32][33];
    __shared__ float si[32][33];
    __shared__ float2 tw[32];

    int img  = blockIdx.x;
    int lane = threadIdx.x;

    float sn, cs;
    __sincosf(6.283185307179586f * (float)lane / 32.f, &sn, &cs);
    tw[lane] = make_float2(cs, sn);

    const float* ip = g_proj + (size_t)img * NTOK;
#pragma unroll
    for (int y = 0; y < 32; y++) {
        sr[y][lane] = ip[(y * 32 + lane) * 2 + 0];
        si[y][lane] = ip[(y * 32 + lane) * 2 + 1];
    }
    __syncwarp();

    float cr[32], ci[32];
#pragma unroll
    for (int j = 0; j < 32; j++) { cr[j] = sr[lane][j]; ci[j] = si[lane][j]; }
    __syncwarp();

    for (int k = 0; k < 32; k++) {
        float ar = 0.f, ai = 0.f;
#pragma unroll
        for (int j = 0; j < 32; j++) {
            float2 w = tw[(j * k) & 31];
            ar += cr[j] * w.x - ci[j] * w.y;
            ai += cr[j] * w.y + ci[j] * w.x;
        }
        sr[k][lane] = ar;
        si[k][lane] = ai;
    }
    __syncwarp();

#pragma unroll
    for (int j = 0; j < 32; j++) { cr[j] = sr[lane][j]; ci[j] = si[lane][j]; }

    float* op = outp + (size_t)img * NTOK;
    for (int k = 0; k < 32; k++) {
        float ar = 0.f, ai = 0.f;
#pragma unroll
        for (int j = 0; j < 32; j++) {
            float2 w = tw[(j * k) & 31];
            ar += cr[j] * w.x - ci[j] * w.y;
            ai += cr[j] * w.y + ci[j] * w.x;
        }
        op[(k * 32 + lane) * 2 + 0] = ar * (1.f / 1024.f);
        op[(k * 32 + lane) * 2 + 1] = ai * (1.f / 1024.f);
    }
}

// ---------------------------------------------------------------------------
extern "C" void kernel_launch(void* const* d_in, const int* in_sizes, int n_in,
                              void* d_out, int out_size) {
    const float* x      = (const float*)d_in[0];
    const float* gn_w   = (const float*)d_in[1];
    const float* gn_b   = (const float*)d_in[2];
    const float* qkv_w  = (const float*)d_in[3];
    const float* qkv_b  = (const float*)d_in[4];
    const float* proj_w = (const float*)d_in[5];
    const float* proj_b = (const float*)d_in[6];
    float* out = (float*)d_out;

    float *p_xr, *p_qkv, *p_attn, *p_proj, *p_alpha, *p_bb;
    cudaGetSymbolAddress((void**)&p_xr,    g_xr);
    cudaGetSymbolAddress((void**)&p_qkv,   g_qkv);
    cudaGetSymbolAddress((void**)&p_attn,  g_attn);
    cudaGetSymbolAddress((void**)&p_proj,  g_proj);
    cudaGetSymbolAddress((void**)&p_alpha, g_alpha);
    cudaGetSymbolAddress((void**)&p_bb,    g_bb);

    cudaFuncSetAttribute(k_attn_b, cudaFuncAttributeMaxDynamicSharedMemorySize, ATT_SMEM);
    cudaFuncSetAttribute(k_gemm_b, cudaFuncAttributeMaxDynamicSharedMemorySize, GEMM_SMEM);

    k_zero_stats<<<1, 512>>>();
    k_fft<<<2048, 32>>>(x);
    k_prep_ab<<<8, 256>>>(gn_w, gn_b);
    k_prep_bb<<<768, 256>>>(qkv_w, qkv_b);
    k_gemm_b<<<dim3(16, 6, 8), 256, GEMM_SMEM>>>(qkv_w, p_xr, p_alpha, p_bb, 768, 1, p_qkv);
    k_attn_b<<<512, 256, ATT_SMEM>>>();
    k_gemm_b<<<dim3(16, 2, 8), 256, GEMM_SMEM>>>(proj_w, p_attn, nullptr, proj_b, 256, 0, p_proj);
    k_ifft<<<2048, 32>>>(out);
}

// round 15
// speedup vs baseline: 3.0815x; 1.0567x over previous
#include <cuda_runtime.h>
#include <cuda_fp16.h>
#include <cstdint>
#include <cstddef>

// ---------------------------------------------------------------------------
// FFTAttention: fft2 -> GroupNorm -> QKV gemm -> attention -> proj -> ifft2
// b=8, c=256, h=w=32, n=2048, heads=4, ch=64.
// GEMMs: fp16 m16n8k16, 2-term (A hi/lo x X_hi).
// QKV gemm epilogue writes Q/K/V pre-packed fp16x2 (Q pre-scaled by
// ch^-0.5 * log2e). Attention: S = QK (1 MMA), P = f16(ex2(S)), O = P*V.
// ---------------------------------------------------------------------------

#define NTOK 2048

__device__ float    g_xr  [8 * 256 * NTOK];
__device__ uint32_t g_qp  [32 * 32 * NTOK];    // [hb][c2][t]  f16x2 pairs along c
__device__ uint32_t g_kp  [32 * 32 * NTOK];    // [hb][c2][s]
__device__ uint32_t g_vp  [32 * 64 * (NTOK/2)];// [hb][c][s2]  f16x2 pairs along s
__device__ float    g_attn[8 * 256 * NTOK];
__device__ float    g_proj[8 * 256 * NTOK];
__device__ float    g_alpha[8 * 256];
__device__ float    g_beta [8 * 256];
__device__ float    g_bb   [8 * 768];
__device__ float    g_stats[512];

#define QSCALE 0.1803368801111f   // ch^-0.5 * log2(e) = 0.125 * 1.4426950

// ---------------- fp16 helpers ----------------
__device__ __forceinline__ uint32_t pack_h(float x0, float x1) {
    uint32_t h;
    asm("cvt.rn.f16x2.f32 %0, %1, %2;" : "=r"(h) : "f"(x1), "f"(x0));
    return h;
}
__device__ __forceinline__ void pack2(float x0, float x1, uint32_t& h, uint32_t& l) {
    asm("cvt.rn.f16x2.f32 %0, %1, %2;" : "=r"(h) : "f"(x1), "f"(x0));
    __half2 hh = *reinterpret_cast<const __half2*>(&h);
    float r0 = x0 - __low2float(hh);
    float r1 = x1 - __high2float(hh);
    asm("cvt.rn.f16x2.f32 %0, %1, %2;" : "=r"(l) : "f"(r1), "f"(r0));
}
__device__ __forceinline__ float ex2(float x) {
    float r;
    asm("ex2.approx.f32 %0, %1;" : "=f"(r) : "f"(x));
    return r;
}
__device__ __forceinline__ void mma16(float* d, const uint32_t* a, const uint32_t* b) {
    asm volatile(
        "mma.sync.aligned.m16n8k16.row.col.f32.f16.f16.f32 "
        "{%0,%1,%2,%3}, {%4,%5,%6,%7}, {%8,%9}, {%0,%1,%2,%3};\n"
        : "+f"(d[0]), "+f"(d[1]), "+f"(d[2]), "+f"(d[3])
        : "r"(a[0]), "r"(a[1]), "r"(a[2]), "r"(a[3]), "r"(b[0]), "r"(b[1]));
}

__global__ void k_zero_stats() { g_stats[threadIdx.x] = 0.f; }

// ---------------------------------------------------------------------------
// Forward FFT2 + groupnorm stats (one warp per (b,c) image)
// ---------------------------------------------------------------------------
__global__ void __launch_bounds__(32) k_fft(const float* __restrict__ x) {
    __shared__ float sr[32][33];
    __shared__ float si[32][33];
    __shared__ float2 tw[32];

    int img  = blockIdx.x;
    int lane = threadIdx.x;

    float sn, cs;
    __sincosf(-6.283185307179586f * (float)lane / 32.f, &sn, &cs);
    tw[lane] = make_float2(cs, sn);

    const float* xin = x + (size_t)img * 1024;
#pragma unroll
    for (int y = 0; y < 32; y++) sr[y][lane] = xin[y * 32 + lane];
    __syncwarp();

    float vr[32];
#pragma unroll
    for (int j = 0; j < 32; j++) vr[j] = sr[lane][j];
    __syncwarp();

    for (int k = 0; k < 32; k++) {
        float ar = 0.f, ai = 0.f;
#pragma unroll
        for (int j = 0; j < 32; j++) {
            float2 w = tw[(j * k) & 31];
            ar += vr[j] * w.x;
            ai += vr[j] * w.y;
        }
        sr[k][lane] = ar;
        si[k][lane] = ai;
    }
    __syncwarp();

    float cr[32], ci[32];
#pragma unroll
    for (int t = 0; t < 32; t++) { cr[t] = sr[lane][t]; ci[t] = si[lane][t]; }

    float* outp = g_xr + (size_t)img * NTOK;
    float sum = 0.f, ssq = 0.f;
    for (int k = 0; k < 32; k++) {
        float ar = 0.f, ai = 0.f;
#pragma unroll
        for (int j = 0; j < 32; j++) {
            float2 w = tw[(j * k) & 31];
            ar += cr[j] * w.x - ci[j] * w.y;
            ai += cr[j] * w.y + ci[j] * w.x;
        }
        outp[(k * 32 + lane) * 2 + 0] = ar;
        outp[(k * 32 + lane) * 2 + 1] = ai;
        sum += ar + ai;
        ssq += ar * ar + ai * ai;
    }

#pragma unroll
    for (int off = 16; off > 0; off >>= 1) {
        sum += __shfl_xor_sync(0xffffffffu, sum, off);
        ssq += __shfl_xor_sync(0xffffffffu, ssq, off);
    }
    if (lane == 0) {
        int b  = img >> 8;
        int ch = img & 255;
        int grp = b * 32 + (ch >> 3);
        atomicAdd(&g_stats[grp * 2 + 0], sum);
        atomicAdd(&g_stats[grp * 2 + 1], ssq);
    }
}

__global__ void k_prep_ab(const float* __restrict__ gn_w, const float* __restrict__ gn_b) {
    int b = blockIdx.x;
    int c = threadIdx.x;
    int grp = b * 32 + (c >> 3);
    float s0 = g_stats[grp * 2 + 0];
    float s1 = g_stats[grp * 2 + 1];
    float mean = s0 * (1.f / 16384.f);
    float var  = s1 * (1.f / 16384.f) - mean * mean;
    float rs   = rsqrtf(var + 1e-5f);
    float w = gn_w[c];
    g_alpha[b * 256 + c] = rs * w;
    g_beta [b * 256 + c] = gn_b[c] - mean * rs * w;
}

__global__ void __launch_bounds__(256) k_prep_bb(const float* __restrict__ qkv_w,
                                                 const float* __restrict__ qkv_b) {
    int w = (blockIdx.x * 256 + threadIdx.x) >> 5;
    int lane = threadIdx.x & 31;
    int b = w / 768, o = w - b * 768;
    const float* wr = qkv_w + (size_t)o * 256;
    const float* be = g_beta + b * 256;
    float acc = 0.f;
#pragma unroll
    for (int c = lane; c < 256; c += 32) acc += wr[c] * be[c];
#pragma unroll
    for (int off = 16; off > 0; off >>= 1) acc += __shfl_xor_sync(0xffffffffu, acc, off);
    if (lane == 0) g_bb[w] = acc + qkv_b[o];
}

// ---------------------------------------------------------------------------
// fp16-2x GEMM. split=1: epilogue packs rows into g_qp/g_kp/g_vp (fp16x2).
// ---------------------------------------------------------------------------
#define GAS 20
#define GBS 136
#define STGS 66
#define GEMM_SMEM (128 * STGS * 4 > (2 * 128 * GAS + 16 * GBS) * 4 ? \
                   128 * STGS * 4 : (2 * 128 * GAS + 16 * GBS) * 4)

__global__ void __launch_bounds__(256, 2) k_gemm_b(
    const float* __restrict__ A, const float* __restrict__ X,
    const float* __restrict__ alpha, const float* __restrict__ bias,
    int M, int biasPerBatch, float* __restrict__ out, int split)
{
    extern __shared__ uint32_t sg[];
    uint32_t* ApH = sg;
    uint32_t* ApL = ApH + 128 * GAS;
    uint32_t* BpH = ApL + 128 * GAS;

    int n0 = blockIdx.x * 128, o0 = blockIdx.y * 128, bb = blockIdx.z;
    int tid = threadIdx.x, lane = tid & 31, wid = tid >> 5;
    int wm = wid >> 2, wn = wid & 3;
    int lq = lane >> 2, lr = lane & 3;
    const float* Xb = X + (size_t)bb * 256 * NTOK;
    bool useAlpha = (alpha != nullptr);

    float acc[4][4][4];
#pragma unroll
    for (int i = 0; i < 4; i++)
#pragma unroll
        for (int j = 0; j < 4; j++)
#pragma unroll
            for (int r = 0; r < 4; r++) acc[i][j][r] = 0.f;

    for (int k0 = 0; k0 < 256; k0 += 32) {
        __syncthreads();
#pragma unroll
        for (int r = 0; r < 2; r++) {
            int idx = tid + r * 256;
            int row = idx >> 2, cq = idx & 3;
            const float* ap = A + (size_t)(o0 + row) * 256 + k0 + cq * 8;
            float4 v0 = *(const float4*)(ap);
            float4 v1 = *(const float4*)(ap + 4);
            uint32_t h[4], l[4];
            pack2(v0.x, v0.y, h[0], l[0]);
            pack2(v0.z, v0.w, h[1], l[1]);
            pack2(v1.x, v1.y, h[2], l[2]);
            pack2(v1.z, v1.w, h[3], l[3]);
            *(uint4*)(ApH + row * GAS + cq * 4) = make_uint4(h[0], h[1], h[2], h[3]);
            *(uint4*)(ApL + row * GAS + cq * 4) = make_uint4(l[0], l[1], l[2], l[3]);
        }
#pragma unroll
        for (int r = 0; r < 2; r++) {
            int idx = tid + r * 256;
            int c2 = idx >> 5, n4 = (idx & 31) << 2;
            const float* xp = Xb + (size_t)(k0 + 2 * c2) * NTOK + n0 + n4;
            float4 x0 = *(const float4*)(xp);
            float4 x1 = *(const float4*)(xp + NTOK);
            if (useAlpha) {
                float a0 = alpha[bb * 256 + k0 + 2 * c2];
                float a1 = alpha[bb * 256 + k0 + 2 * c2 + 1];
                x0.x *= a0; x0.y *= a0; x0.z *= a0; x0.w *= a0;
                x1.x *= a1; x1.y *= a1; x1.z *= a1; x1.w *= a1;
            }
            uint32_t h[4];
            h[0] = pack_h(x0.x, x1.x);
            h[1] = pack_h(x0.y, x1.y);
            h[2] = pack_h(x0.z, x1.z);
            h[3] = pack_h(x0.w, x1.w);
            *(uint4*)(BpH + c2 * GBS + n4) = make_uint4(h[0], h[1], h[2], h[3]);
        }
        __syncthreads();

#pragma unroll
        for (int ks = 0; ks < 2; ks++) {
            uint32_t ah[4][4], al_[4][4];
#pragma unroll
            for (int mf = 0; mf < 4; mf++) {
                int m = wm * 64 + mf * 16 + lq;
                int r0 = m * GAS + ks * 8 + lr;
                int r1 = r0 + 4;
                ah[mf][0] = ApH[r0]; ah[mf][1] = ApH[r0 + 8 * GAS];
                ah[mf][2] = ApH[r1]; ah[mf][3] = ApH[r1 + 8 * GAS];
                al_[mf][0] = ApL[r0]; al_[mf][1] = ApL[r0 + 8 * GAS];
                al_[mf][2] = ApL[r1]; al_[mf][3] = ApL[r1 + 8 * GAS];
            }
#pragma unroll
            for (int nf = 0; nf < 4; nf++) {
                int n = wn * 32 + nf * 8 + lq;
                int b0i = (ks * 8 + lr) * GBS + n;
                int b1i = (ks * 8 + 4 + lr) * GBS + n;
                uint32_t bh[2] = {BpH[b0i], BpH[b1i]};
#pragma unroll
                for (int mf = 0; mf < 4; mf++) {
                    mma16(acc[mf][nf], ah[mf], bh);
                    mma16(acc[mf][nf], al_[mf], bh);
                }
            }
        }
    }

    if (split) {
        // stage all q/k rows as packed f16x2 of (n, n+1); V rows go direct.
        uint32_t* stg = sg;   // [128 rows][STGS]
        __syncthreads();
#pragma unroll
        for (int mf = 0; mf < 4; mf++) {
#pragma unroll
            for (int rr = 0; rr < 2; rr++) {
                int o = o0 + wm * 64 + mf * 16 + lq + rr * 8;
                int h = o / 192, rm = o - h * 192;
                float bv = bias[bb * 768 + o];
                float scl = (rm < 64) ? QSCALE : 1.f;
                size_t hb = (size_t)(bb * 4 + h);
#pragma unroll
                for (int nf = 0; nf < 4; nf++) {
                    int n = n0 + wn * 32 + nf * 8 + 2 * lr;
                    float v0 = (acc[mf][nf][rr * 2 + 0] + bv) * scl;
                    float v1 = (acc[mf][nf][rr * 2 + 1] + bv) * scl;
                    uint32_t pk = pack_h(v0, v1);
                    if (rm >= 128) {
                        g_vp[(hb * 64 + (rm - 128)) * (NTOK / 2) + (n >> 1)] = pk;
                    } else {
                        stg[(o - o0) * STGS + ((n - n0) >> 1)] = pk;
                    }
                }
            }
        }
        __syncthreads();
        // pair-combine rows (2c, 2c+1) -> c-pair-packed, t-major
#pragma unroll
        for (int i = 0; i < 16; i++) {
            int idx = tid + i * 256;
            int c2l = idx >> 6, n2 = idx & 63;
            int o = o0 + 2 * c2l;
            int h = o / 192, rm = o - h * 192;
            if (rm < 128) {
                uint32_t s0v = stg[(2 * c2l) * STGS + n2];
                uint32_t s1v = stg[(2 * c2l + 1) * STGS + n2];
                uint32_t e0 = __byte_perm(s0v, s1v, 0x5410);   // (row0.n, row1.n)
                uint32_t e1 = __byte_perm(s0v, s1v, 0x7632);   // (row0.n+1, row1.n+1)
                size_t hb = (size_t)(bb * 4 + h);
                uint32_t* dst = (rm < 64) ? g_qp : g_kp;
                int c2g = (rm < 64 ? rm : rm - 64) >> 1;
                *(uint2*)(dst + (hb * 32 + c2g) * NTOK + n0 + 2 * n2) = make_uint2(e0, e1);
            }
        }
    } else {
#pragma unroll
        for (int mf = 0; mf < 4; mf++) {
            int o = o0 + wm * 64 + mf * 16 + lq;
            float b0 = biasPerBatch ? bias[bb * M + o] : bias[o];
            float b1 = biasPerBatch ? bias[bb * M + o + 8] : bias[o + 8];
#pragma unroll
            for (int nf = 0; nf < 4; nf++) {
                int n = n0 + wn * 32 + nf * 8 + 2 * lr;
                float2 v0 = make_float2(acc[mf][nf][0] + b0, acc[mf][nf][1] + b0);
                float2 v1 = make_float2(acc[mf][nf][2] + b1, acc[mf][nf][3] + b1);
                *(float2*)(out + ((size_t)bb * M + o) * NTOK + n) = v0;
                *(float2*)(out + ((size_t)bb * M + o + 8) * NTOK + n) = v1;
            }
        }
    }
}

// ---------------------------------------------------------------------------
// Attention (fp16, pre-packed inputs). S = Q x K (1 MMA, log2-domain);
// P = f16(ex2(S)); O^T = P x V (1 MMA). 8 warps, occ 2. No cvt in chunk loop.
// ---------------------------------------------------------------------------
#define QKS 136    // Qp/Kp stride (uint32), rows = c2 (32)
#define VS2 68     // Vp stride (uint32), rows = c (64)
#define PS2 68     // Ps stride (uint32), rows = t (128)
#define PFP 136    // float-view stride for final transpose
#define ATT_SMEM ((2 * 32 * QKS + 64 * VS2 + 128 * PS2) * 4 + 512)

__global__ void __launch_bounds__(256, 2) k_attn_b() {
    extern __shared__ uint32_t su[];
    uint32_t* QpH = su;                    // [32 c2][QKS t]
    uint32_t* KpH = QpH + 32 * QKS;        // [32 c2][QKS s]
    uint32_t* VpH = KpH + 32 * QKS;        // [64 c][VS2 s2]
    uint32_t* PsH = VpH + 64 * VS2;        // [128 t][PS2 s2]
    float*    Ls  = (float*)(PsH + 128 * PS2);

    int hb = blockIdx.x >> 4, qt = blockIdx.x & 15;
    const uint32_t* qp = g_qp + (size_t)hb * 32 * NTOK;
    const uint32_t* kp = g_kp + (size_t)hb * 32 * NTOK;
    const uint32_t* vp = g_vp + (size_t)hb * 64 * (NTOK / 2);
    int tid = threadIdx.x, lane = tid & 31, wid = tid >> 5;
    int wt = wid >> 1, ws = wid & 1;
    int lq = lane >> 2, lr = lane & 3;
    int t0 = qt * 128;

    if (tid < 128) Ls[tid] = 0.f;

    // Q tile: direct packed copy
#pragma unroll
    for (int r = 0; r < 4; r++) {
        int idx = tid + r * 256;
        int c2 = idx >> 5, t4 = (idx & 31) << 2;
        uint4 v = *(const uint4*)(qp + c2 * NTOK + t0 + t4);
        *(uint4*)(QpH + c2 * QKS + t4) = v;
    }

    float accO[8][4];
#pragma unroll
    for (int i = 0; i < 8; i++)
#pragma unroll
        for (int r = 0; r < 4; r++) accO[i][r] = 0.f;
    float lsum[4] = {0.f, 0.f, 0.f, 0.f};

    for (int st = 0; st < 16; st++) {
        int s0 = st * 128;
        // K tile: direct packed copy
#pragma unroll
        for (int r = 0; r < 4; r++) {
            int idx = tid + r * 256;
            int c2 = idx >> 5, s4 = (idx & 31) << 2;
            uint4 v = *(const uint4*)(kp + c2 * NTOK + s0 + s4);
            *(uint4*)(KpH + c2 * QKS + s4) = v;
        }
        // V tile: direct packed copy (2x uint2 stores keep VS2=68 alignment)
#pragma unroll
        for (int r = 0; r < 4; r++) {
            int idx = tid + r * 256;
            int c = idx >> 4, s2q = (idx & 15) << 2;
            uint4 v = *(const uint4*)(vp + c * (NTOK / 2) + (s0 >> 1) + s2q);
            *(uint2*)(VpH + c * VS2 + s2q)     = make_uint2(v.x, v.y);
            *(uint2*)(VpH + c * VS2 + s2q + 2) = make_uint2(v.z, v.w);
        }
        __syncthreads();

        // ------- phase 1: S = Q^T K, two 32-column halves per warp -------
#pragma unroll
        for (int half = 0; half < 2; half++) {
            float accS[2][4][4];
#pragma unroll
            for (int i = 0; i < 2; i++)
#pragma unroll
                for (int j = 0; j < 4; j++)
#pragma unroll
                    for (int r = 0; r < 4; r++) accS[i][j][r] = 0.f;

#pragma unroll
            for (int ks = 0; ks < 4; ks++) {
                uint32_t ah[2][4];
#pragma unroll
                for (int mf = 0; mf < 2; mf++) {
                    int t = wt * 32 + mf * 16 + lq;
                    int r0 = (ks * 8 + lr) * QKS + t;
                    int r1 = (ks * 8 + 4 + lr) * QKS + t;
                    ah[mf][0] = QpH[r0]; ah[mf][1] = QpH[r0 + 8];
                    ah[mf][2] = QpH[r1]; ah[mf][3] = QpH[r1 + 8];
                }
#pragma unroll
                for (int nf = 0; nf < 4; nf++) {
                    int s = ws * 64 + half * 32 + nf * 8 + lq;
                    int b0i = (ks * 8 + lr) * QKS + s;
                    int b1i = (ks * 8 + 4 + lr) * QKS + s;
                    uint32_t bh[2] = {KpH[b0i], KpH[b1i]};
#pragma unroll
                    for (int mf = 0; mf < 2; mf++)
                        mma16(accS[mf][nf], ah[mf], bh);
                }
            }

            // ex2 (log2-domain logits), row sums, pack P pairs along s
#pragma unroll
            for (int mf = 0; mf < 2; mf++) {
                int t = wt * 32 + mf * 16 + lq;
#pragma unroll
                for (int nf = 0; nf < 4; nf++) {
                    int s2 = ws * 32 + half * 16 + nf * 4 + lr;
                    float e0 = ex2(accS[mf][nf][0]);
                    float e1 = ex2(accS[mf][nf][1]);
                    float e2 = ex2(accS[mf][nf][2]);
                    float e3 = ex2(accS[mf][nf][3]);
                    lsum[mf * 2 + 0] += e0 + e1;
                    lsum[mf * 2 + 1] += e2 + e3;
                    PsH[t * PS2 + s2]       = pack_h(e0, e1);
                    PsH[(t + 8) * PS2 + s2] = pack_h(e2, e3);
                }
            }
        }
        __syncthreads();

        // ------- phase 2: O^T[t][c] += P[t][s] * V[c][s] (1 MMA) -------
        int tb = wid * 16 + lq;
#pragma unroll
        for (int ks = 0; ks < 8; ks++) {
            int p0 = tb * PS2 + ks * 8 + lr;
            uint32_t ah[4];
            ah[0] = PsH[p0];     ah[1] = PsH[p0 + 8 * PS2];
            ah[2] = PsH[p0 + 4]; ah[3] = PsH[p0 + 8 * PS2 + 4];
#pragma unroll
            for (int nf = 0; nf < 8; nf++) {
                int c = nf * 8 + lq;
                int b0i = c * VS2 + ks * 8 + lr;
                uint32_t bh[2] = {VpH[b0i], VpH[b0i + 4]};
                mma16(accO[nf], ah, bh);
            }
        }
        __syncthreads();
    }

    // reduce row sums into Ls
#pragma unroll
    for (int i = 0; i < 4; i++) {
        lsum[i] += __shfl_xor_sync(0xffffffffu, lsum[i], 1);
        lsum[i] += __shfl_xor_sync(0xffffffffu, lsum[i], 2);
    }
    if (lr == 0) {
        atomicAdd(&Ls[wt * 32 + lq],          lsum[0]);
        atomicAdd(&Ls[wt * 32 + lq + 8],      lsum[1]);
        atomicAdd(&Ls[wt * 32 + 16 + lq],     lsum[2]);
        atomicAdd(&Ls[wt * 32 + 16 + lq + 8], lsum[3]);
    }
    __syncthreads();

    // normalize + transpose via float scratch (overwrites Q/K tiles)
    float* Pf = (float*)su;    // [64 c][PFP t]
    float inv0 = 1.f / Ls[wid * 16 + lq];
    float inv1 = 1.f / Ls[wid * 16 + lq + 8];
    int t = wid * 16 + lq;
#pragma unroll
    for (int nf = 0; nf < 8; nf++) {
        int cc = nf * 8 + 2 * lr;
        Pf[cc * PFP + t]           = accO[nf][0] * inv0;
        Pf[(cc + 1) * PFP + t]     = accO[nf][1] * inv0;
        Pf[cc * PFP + t + 8]       = accO[nf][2] * inv1;
        Pf[(cc + 1) * PFP + t + 8] = accO[nf][3] * inv1;
    }
    __syncthreads();

    int rowbase = hb * 64;
#pragma unroll
    for (int r = 0; r < 8; r++) {
        int idx = tid + r * 256;
        int c = idx >> 5, t4 = (idx & 31) << 2;
        float4 v = *(const float4*)(Pf + c * PFP + t4);
        *(float4*)(g_attn + (size_t)(rowbase + c) * NTOK + t0 + t4) = v;
    }
}

// ---------------------------------------------------------------------------
// Inverse FFT2
// ---------------------------------------------------------------------------
__global__ void __launch_bounds__(32) k_ifft(float* __restrict__ outp) {
    __shared__ float sr[32][33];
    __shared__ float si[32][33];
    __shared__ float2 tw[32];

    int img  = blockIdx.x;
    int lane = threadIdx.x;

    float sn, cs;
    __sincosf(6.283185307179586f * (float)lane / 32.f, &sn, &cs);
    tw[lane] = make_float2(cs, sn);

    const float* ip = g_proj + (size_t)img * NTOK;
#pragma unroll
    for (int y = 0; y < 32; y++) {
        sr[y][lane] = ip[(y * 32 + lane) * 2 + 0];
        si[y][lane] = ip[(y * 32 + lane) * 2 + 1];
    }
    __syncwarp();

    float cr[32], ci[32];
#pragma unroll
    for (int j = 0; j < 32; j++) { cr[j] = sr[lane][j]; ci[j] = si[lane][j]; }
    __syncwarp();

    for (int k = 0; k < 32; k++) {
        float ar = 0.f, ai = 0.f;
#pragma unroll
        for (int j = 0; j < 32; j++) {
            float2 w = tw[(j * k) & 31];
            ar += cr[j] * w.x - ci[j] * w.y;
            ai += cr[j] * w.y + ci[j] * w.x;
        }
        sr[k][lane] = ar;
        si[k][lane] = ai;
    }
    __syncwarp();

#pragma unroll
    for (int j = 0; j < 32; j++) { cr[j] = sr[lane][j]; ci[j] = si[lane][j]; }

    float* op = outp + (size_t)img * NTOK;
    for (int k = 0; k < 32; k++) {
        float ar = 0.f, ai = 0.f;
#pragma unroll
        for (int j = 0; j < 32; j++) {
            float2 w = tw[(j * k) & 31];
            ar += cr[j] * w.x - ci[j] * w.y;
            ai += cr[j] * w.y + ci[j] * w.x;
        }
        op[(k * 32 + lane) * 2 + 0] = ar * (1.f / 1024.f);
        op[(k * 32 + lane) * 2 + 1] = ai * (1.f / 1024.f);
    }
}

// ---------------------------------------------------------------------------
extern "C" void kernel_launch(void* const* d_in, const int* in_sizes, int n_in,
                              void* d_out, int out_size) {
    const float* x      = (const float*)d_in[0];
    const float* gn_w   = (const float*)d_in[1];
    const float* gn_b   = (const float*)d_in[2];
    const float* qkv_w  = (const float*)d_in[3];
    const float* qkv_b  = (const float*)d_in[4];
    const float* proj_w = (const float*)d_in[5];
    const float* proj_b = (const float*)d_in[6];
    float* out = (float*)d_out;

    float *p_xr, *p_attn, *p_proj, *p_alpha, *p_bb;
    cudaGetSymbolAddress((void**)&p_xr,    g_xr);
    cudaGetSymbolAddress((void**)&p_attn,  g_attn);
    cudaGetSymbolAddress((void**)&p_proj,  g_proj);
    cudaGetSymbolAddress((void**)&p_alpha, g_alpha);
    cudaGetSymbolAddress((void**)&p_bb,    g_bb);

    cudaFuncSetAttribute(k_attn_b, cudaFuncAttributeMaxDynamicSharedMemorySize, ATT_SMEM);
    cudaFuncSetAttribute(k_gemm_b, cudaFuncAttributeMaxDynamicSharedMemorySize, GEMM_SMEM);

    k_zero_stats<<<1, 512>>>();
    k_fft<<<2048, 32>>>(x);
    k_prep_ab<<<8, 256>>>(gn_w, gn_b);
    k_prep_bb<<<768, 256>>>(qkv_w, qkv_b);
    // QKV gemm: split epilogue -> packed fp16 Q/K/V
    k_gemm_b<<<dim3(16, 6, 8), 256, GEMM_SMEM>>>(qkv_w, p_xr, p_alpha, p_bb, 768, 1,
                                                 nullptr, 1);
    k_attn_b<<<512, 256, ATT_SMEM>>>();
    k_gemm_b<<<dim3(16, 2, 8), 256, GEMM_SMEM>>>(proj_w, p_attn, nullptr, proj_b, 256, 0,
                                                 p_proj, 0);
    k_ifft<<<2048, 32>>>(out);
}